// round 12
// baseline (speedup 1.0000x reference)
#include <cuda_runtime.h>
#include <math.h>

#define B_  2
#define S_  2048
#define D_  2048
#define H_  16
#define HD_ 128

#define MK_ACT ((size_t)4096 * 2048)
#define MK_W   ((size_t)2048 * 2048)

// ---------------- scratch (device globals: no allocation allowed) -------------
__device__ float g_Q[(size_t)B_ * H_ * S_ * HD_];   // [B,H,S,hd]
__device__ float g_K[(size_t)B_ * H_ * S_ * HD_];
__device__ float g_V[(size_t)B_ * H_ * S_ * HD_];
__device__ float g_att[(size_t)B_ * S_ * D_];       // [B,S,D] attention output
__device__ float g_cos[S_ * 64];
__device__ float g_sin[S_ * 64];
// tf32 hi/lo pre-split buffers (3 slots each for QKV batching)
__device__ unsigned g_actH[3 * MK_ACT];
__device__ unsigned g_actL[3 * MK_ACT];
__device__ unsigned g_wH[3 * MK_W];
__device__ unsigned g_wL[3 * MK_W];

// ---------------- RoPE tables -------------------------------------------------
__global__ void rope_tables_kernel() {
    int idx = blockIdx.x * blockDim.x + threadIdx.x;
    if (idx >= S_ * 64) return;
    int s = idx >> 6, j = idx & 63;
    float invf = (float)(1.0 / pow(10000.0, (double)(2 * j) / 128.0));
    float ang_f = (float)s * invf;
    double ang = (double)ang_f;
    g_cos[idx] = (float)cos(ang);
    g_sin[idx] = (float)sin(ang);
}

__global__ void rope_apply_kernel() {
    int idx = blockIdx.x * blockDim.x + threadIdx.x;
    const int total = B_ * H_ * S_ * 64;
    float* T = (idx < total) ? g_Q : g_K;
    int p = (idx < total) ? idx : idx - total;
    int j = p & 63;
    int row = p >> 6;                // (b*H + h)*S + s
    int s = row & (S_ - 1);
    size_t base = (size_t)row * HD_ + j;
    float c  = g_cos[(s << 6) + j];
    float sn = g_sin[(s << 6) + j];
    float x0 = T[base];
    float x1 = T[base + 64];
    T[base]      = x0 * c - x1 * sn;
    T[base + 64] = x1 * c + x0 * sn;
}

// ---------------- helpers ------------------------------------------------------
__device__ __forceinline__ void tf32_split(float x, unsigned &h, unsigned &l) {
    asm("cvt.rna.tf32.f32 %0, %1;" : "=r"(h) : "f"(x));
    float lf = x - __uint_as_float(h);    // exact (tf32 subset of fp32)
    asm("cvt.rna.tf32.f32 %0, %1;" : "=r"(l) : "f"(lf));
}

__device__ __forceinline__ void mma_tf32(float* c, const unsigned* a, const unsigned* b) {
    asm volatile(
        "mma.sync.aligned.m16n8k8.row.col.f32.tf32.tf32.f32 "
        "{%0,%1,%2,%3}, {%4,%5,%6,%7}, {%8,%9}, {%0,%1,%2,%3};"
        : "+f"(c[0]), "+f"(c[1]), "+f"(c[2]), "+f"(c[3])
        : "r"(a[0]), "r"(a[1]), "r"(a[2]), "r"(a[3]), "r"(b[0]), "r"(b[1]));
}

__device__ __forceinline__ void cp16(unsigned dst, const void* src) {
    asm volatile("cp.async.cg.shared.global [%0], [%1], 16;" :: "r"(dst), "l"(src));
}

// ---------------- hi/lo split pass ---------------------------------------------
__global__ void __launch_bounds__(256) split_kernel(
    const float4* __restrict__ src, uint4* __restrict__ h4,
    uint4* __restrict__ l4, int n4)
{
    int i = blockIdx.x * blockDim.x + threadIdx.x;
    if (i >= n4) return;
    float4 v = src[i];
    unsigned h0,h1,h2,h3,l0,l1,l2,l3;
    tf32_split(v.x, h0, l0); tf32_split(v.y, h1, l1);
    tf32_split(v.z, h2, l2); tf32_split(v.w, h3, l3);
    h4[i] = make_uint4(h0,h1,h2,h3);
    l4[i] = make_uint4(l0,l1,l2,l3);
}

// ---------------- 3xTF32 cp.async pipelined GEMM --------------------------------
// C[m,n] = sum_k A[m,k]*W[n,k], operands pre-split to tf32 hi/lo in gmem.
// 128x128 tile, BK=32, 256 threads (8 warps 2x4, warp 64x32), 3-stage cp.async.
// grid.z selects operand slot. mode 1: head layout into g_Q/g_K/g_V by z.
#define TPAD 36
#define TSMW 4608                       // words per component per stage (128*36)
#define STW  (4 * TSMW)                 // words per stage
#define STB  (STW * 4)                  // bytes per stage (73728)
#define GEMM_SMEM_BYTES (3 * STB)       // 221184

__global__ void __launch_bounds__(256) gemm3_kernel(
    const unsigned* __restrict__ AhB, const unsigned* __restrict__ AlB,
    const unsigned* __restrict__ WhB, const unsigned* __restrict__ WlB,
    float* __restrict__ Cout, int mode)
{
    extern __shared__ unsigned smu[];
    unsigned smb = (unsigned)__cvta_generic_to_shared(smu);

    const int K = D_;
    int z = blockIdx.z;
    int tid = threadIdx.x, lane = tid & 31, warp = tid >> 5;
    int wm = (warp & 1) * 64, wn = (warp >> 1) * 32;
    int gid = lane >> 2, tig = lane & 3;
    int m0 = blockIdx.y * 128, n0 = blockIdx.x * 128;

    const unsigned* Ahp = AhB + (size_t)z * MK_ACT + (size_t)m0 * K;
    const unsigned* Alp = AlB + (size_t)z * MK_ACT + (size_t)m0 * K;
    const unsigned* Whp = WhB + (size_t)z * MK_W + (size_t)n0 * K;
    const unsigned* Wlp = WlB + (size_t)z * MK_W + (size_t)n0 * K;

    int ldrow = tid >> 3;               // 0..31
    int ldcol = (tid & 7) << 2;         // 0..28 step 4

    float acc[4][4][4];
#pragma unroll
    for (int mt = 0; mt < 4; mt++)
#pragma unroll
        for (int nt = 0; nt < 4; nt++)
#pragma unroll
            for (int e = 0; e < 4; e++) acc[mt][nt][e] = 0.f;

    const int NCHUNK = K / 32;          // 64

    // issue stage copy for chunk c into buffer st (always commits a group)
    auto issue = [&](int c, int st) {
        if (c < NCHUNK) {
            unsigned sb = smb + st * STB;
#pragma unroll
            for (int r = 0; r < 4; r++) {
                int row = ldrow + 32 * r;
                size_t g = (size_t)row * K + c * 32 + ldcol;
                unsigned so = sb + (row * TPAD + ldcol) * 4;
                cp16(so,                Ahp + g);
                cp16(so + TSMW * 4,     Alp + g);
                cp16(so + TSMW * 8,     Whp + g);
                cp16(so + TSMW * 12,    Wlp + g);
            }
        }
        asm volatile("cp.async.commit_group;");
    };

    issue(0, 0);
    issue(1, 1);

    for (int c = 0; c < NCHUNK; c++) {
        int st = c % 3;
        asm volatile("cp.async.wait_group 1;");
        __syncthreads();
        issue(c + 2, (c + 2) % 3);

        const unsigned* AsH = smu + st * STW;
        const unsigned* AsL = AsH + TSMW;
        const unsigned* WsH = AsL + TSMW;
        const unsigned* WsL = WsH + TSMW;

#pragma unroll
        for (int ks = 0; ks < 4; ks++) {
            int k0 = ks * 8;
            unsigned ah[4][4], al[4][4], bh[4][2], bl[4][2];
#pragma unroll
            for (int mt = 0; mt < 4; mt++) {
                int base = (wm + mt * 16 + gid) * TPAD + k0 + tig;
                ah[mt][0] = AsH[base];
                ah[mt][1] = AsH[base + 8 * TPAD];
                ah[mt][2] = AsH[base + 4];
                ah[mt][3] = AsH[base + 8 * TPAD + 4];
                al[mt][0] = AsL[base];
                al[mt][1] = AsL[base + 8 * TPAD];
                al[mt][2] = AsL[base + 4];
                al[mt][3] = AsL[base + 8 * TPAD + 4];
            }
#pragma unroll
            for (int nt = 0; nt < 4; nt++) {
                int base = (wn + nt * 8 + gid) * TPAD + k0 + tig;
                bh[nt][0] = WsH[base];
                bh[nt][1] = WsH[base + 4];
                bl[nt][0] = WsL[base];
                bl[nt][1] = WsL[base + 4];
            }
#pragma unroll
            for (int mt = 0; mt < 4; mt++)
#pragma unroll
                for (int nt = 0; nt < 4; nt++) {
                    mma_tf32(acc[mt][nt], ah[mt], bh[nt]);
                    mma_tf32(acc[mt][nt], ah[mt], bl[nt]);
                    mma_tf32(acc[mt][nt], al[mt], bh[nt]);
                }
        }
    }

    float* C = (mode == 0) ? Cout : (z == 0 ? g_Q : (z == 1 ? g_K : g_V));

#pragma unroll
    for (int mt = 0; mt < 4; mt++) {
#pragma unroll
        for (int nt = 0; nt < 4; nt++) {
            int m = m0 + wm + mt * 16 + gid;
            int n = n0 + wn + nt * 8 + 2 * tig;
            float2 v0 = make_float2(acc[mt][nt][0], acc[mt][nt][1]);
            float2 v1 = make_float2(acc[mt][nt][2], acc[mt][nt][3]);
            if (mode == 0) {
                *(float2*)&C[(size_t)m * D_ + n]       = v0;
                *(float2*)&C[(size_t)(m + 8) * D_ + n] = v1;
            } else {
                int h = n >> 7, d = n & 127;
                int b = m >> 11, s = m & (S_ - 1);
                *(float2*)&C[(((size_t)b * H_ + h) * S_ + s) * HD_ + d] = v0;
                int m8 = m + 8;
                int b8 = m8 >> 11, s8 = m8 & (S_ - 1);
                *(float2*)&C[(((size_t)b8 * H_ + h) * S_ + s8) * HD_ + d] = v1;
            }
        }
    }
}

// ---------------- 3xTF32 tensor-core flash attention ---------------------------
#define AOFF_KH 16896
#define AOFF_KL (16896 + 8448)
#define AOFF_P  16896
#define AOFF_VH 33792
#define AOFF_VL 42496
#define AOFF_FLAG 51200
#define ATT_SMEM_BYTES ((51200 + 8) * 4)

__global__ void __launch_bounds__(256) attn_tc_kernel(const int* __restrict__ mask)
{
    extern __shared__ float sm[];
    float*    Qs  = sm;
    unsigned* Kh  = (unsigned*)(sm + AOFF_KH);
    unsigned* Kl  = (unsigned*)(sm + AOFF_KL);
    unsigned* Vh  = (unsigned*)(sm + AOFF_VH);
    unsigned* Vl  = (unsigned*)(sm + AOFF_VL);
    float*    Ps  = sm + AOFF_P;
    int*    flagp = (int*)(sm + AOFF_FLAG);

    int bh = blockIdx.y;
    int b = bh >> 4, h = bh & 15;
    int q0 = blockIdx.x * 128;
    int tid = threadIdx.x;
    int lane = tid & 31;
    int warp = tid >> 5;
    int gid = lane >> 2, tig = lane & 3;
    int wm = warp * 16;
    const float scale = 0.08838834764831843f;   // 1/sqrt(128)

    const float* Qg = g_Q + (size_t)bh * S_ * HD_ + (size_t)q0 * HD_;
    const float* Kg = g_K + (size_t)bh * S_ * HD_;
    const float* Vg = g_V + (size_t)bh * S_ * HD_;
    const int*   Mg = mask + (size_t)b * S_ * S_ + (size_t)q0 * S_;

#pragma unroll
    for (int r = 0; r < 16; r++) {
        int idx = tid + 256 * r;
        int row = idx >> 5;
        int col = (idx & 31) << 2;
        float4 v = *(const float4*)(Qg + (size_t)row * HD_ + col);
        float* dst = Qs + row * 132 + col;
        dst[0] = v.x * scale; dst[1] = v.y * scale;
        dst[2] = v.z * scale; dst[3] = v.w * scale;
    }

    float m0 = -INFINITY, m1 = -INFINITY, l0 = 0.f, l1 = 0.f;
    float accO[16][4];
#pragma unroll
    for (int nt = 0; nt < 16; nt++)
#pragma unroll
        for (int e = 0; e < 4; e++) accO[nt][e] = 0.f;

    for (int kt = 0; kt < S_; kt += 64) {
        __syncthreads();
        bool ok = true;
#pragma unroll
        for (int r = 0; r < 8; r++) {
            int idx = tid + 256 * r;
            int row = idx >> 5;
            int col = (idx & 31) << 2;
            float4 kv = *(const float4*)(Kg + (size_t)(kt + row) * HD_ + col);
            unsigned h0,h1,h2,h3,l0_,l1_,l2_,l3_;
            tf32_split(kv.x, h0, l0_); tf32_split(kv.y, h1, l1_);
            tf32_split(kv.z, h2, l2_); tf32_split(kv.w, h3, l3_);
            *(uint4*)&Kh[row * 132 + col] = make_uint4(h0,h1,h2,h3);
            *(uint4*)&Kl[row * 132 + col] = make_uint4(l0_,l1_,l2_,l3_);
            float4 vv = *(const float4*)(Vg + (size_t)(kt + row) * HD_ + col);
            tf32_split(vv.x, h0, l0_); tf32_split(vv.y, h1, l1_);
            tf32_split(vv.z, h2, l2_); tf32_split(vv.w, h3, l3_);
            *(uint4*)&Vh[row * 136 + col] = make_uint4(h0,h1,h2,h3);
            *(uint4*)&Vl[row * 136 + col] = make_uint4(l0_,l1_,l2_,l3_);
        }
#pragma unroll
        for (int r = 0; r < 8; r++) {
            int idx = tid + 256 * r;
            int mrow = idx >> 4;
            int mc = (idx & 15) << 2;
            int4 mm = *(const int4*)(Mg + (size_t)mrow * S_ + kt + mc);
            ok = ok && (mm.x != 0) && (mm.y != 0) && (mm.z != 0) && (mm.w != 0);
        }
        unsigned bal = __ballot_sync(0xffffffffu, ok);
        if (lane == 0) flagp[warp] = (bal == 0xffffffffu) ? 1 : 0;
        __syncthreads();
        int allones = flagp[0] & flagp[1] & flagp[2] & flagp[3]
                    & flagp[4] & flagp[5] & flagp[6] & flagp[7];

        float sacc[8][4];
#pragma unroll
        for (int nt = 0; nt < 8; nt++)
#pragma unroll
            for (int e = 0; e < 4; e++) sacc[nt][e] = 0.f;

#pragma unroll
        for (int ks = 0; ks < 16; ks++) {
            int k0 = ks * 8;
            const float* qb = Qs + (wm + gid) * 132 + k0 + tig;
            unsigned ah[4], al[4];
            tf32_split(qb[0],          ah[0], al[0]);
            tf32_split(qb[8 * 132],    ah[1], al[1]);
            tf32_split(qb[4],          ah[2], al[2]);
            tf32_split(qb[8 * 132 + 4],ah[3], al[3]);
#pragma unroll
            for (int nt = 0; nt < 8; nt++) {
                const unsigned* kb  = Kh + (nt * 8 + gid) * 132 + k0 + tig;
                const unsigned* klb = Kl + (nt * 8 + gid) * 132 + k0 + tig;
                unsigned bh[2] = { kb[0], kb[4] };
                unsigned bl[2] = { klb[0], klb[4] };
                mma_tf32(sacc[nt], ah, bh);
                mma_tf32(sacc[nt], ah, bl);
                mma_tf32(sacc[nt], al, bh);
            }
        }

        if (!allones) {
            const int* M2 = mask + (size_t)b * S_ * S_;
#pragma unroll
            for (int nt = 0; nt < 8; nt++)
#pragma unroll
                for (int v = 0; v < 4; v++) {
                    int row = q0 + wm + gid + ((v >> 1) << 3);
                    int col = kt + nt * 8 + 2 * tig + (v & 1);
                    if (M2[(size_t)row * S_ + col] == 0) sacc[nt][v] = -1e30f;
                }
        }

        float mx0 = -INFINITY, mx1 = -INFINITY;
#pragma unroll
        for (int nt = 0; nt < 8; nt++) {
            mx0 = fmaxf(mx0, fmaxf(sacc[nt][0], sacc[nt][1]));
            mx1 = fmaxf(mx1, fmaxf(sacc[nt][2], sacc[nt][3]));
        }
        mx0 = fmaxf(mx0, __shfl_xor_sync(0xffffffffu, mx0, 1));
        mx0 = fmaxf(mx0, __shfl_xor_sync(0xffffffffu, mx0, 2));
        mx1 = fmaxf(mx1, __shfl_xor_sync(0xffffffffu, mx1, 1));
        mx1 = fmaxf(mx1, __shfl_xor_sync(0xffffffffu, mx1, 2));
        float mn0 = fmaxf(m0, mx0), mn1 = fmaxf(m1, mx1);
        float c0 = __expf(m0 - mn0), c1 = __expf(m1 - mn1);
        m0 = mn0; m1 = mn1;
        float s0 = 0.f, s1 = 0.f;
#pragma unroll
        for (int nt = 0; nt < 8; nt++) {
            sacc[nt][0] = __expf(sacc[nt][0] - mn0);
            sacc[nt][1] = __expf(sacc[nt][1] - mn0);
            sacc[nt][2] = __expf(sacc[nt][2] - mn1);
            sacc[nt][3] = __expf(sacc[nt][3] - mn1);
            s0 += sacc[nt][0] + sacc[nt][1];
            s1 += sacc[nt][2] + sacc[nt][3];
        }
        s0 += __shfl_xor_sync(0xffffffffu, s0, 1);
        s0 += __shfl_xor_sync(0xffffffffu, s0, 2);
        s1 += __shfl_xor_sync(0xffffffffu, s1, 1);
        s1 += __shfl_xor_sync(0xffffffffu, s1, 2);
        l0 = l0 * c0 + s0;
        l1 = l1 * c1 + s1;
#pragma unroll
        for (int nt = 0; nt < 16; nt++) {
            accO[nt][0] *= c0; accO[nt][1] *= c0;
            accO[nt][2] *= c1; accO[nt][3] *= c1;
        }

        __syncthreads();
#pragma unroll
        for (int nt = 0; nt < 8; nt++) {
            *(float2*)(Ps + (wm + gid) * 68 + nt * 8 + 2 * tig) =
                make_float2(sacc[nt][0], sacc[nt][1]);
            *(float2*)(Ps + (wm + 8 + gid) * 68 + nt * 8 + 2 * tig) =
                make_float2(sacc[nt][2], sacc[nt][3]);
        }
        __syncwarp();

#pragma unroll
        for (int ks = 0; ks < 8; ks++) {
            int k0 = ks * 8;
            const float* pb = Ps + (wm + gid) * 68 + k0 + tig;
            unsigned ph[4], pl[4];
            tf32_split(pb[0],          ph[0], pl[0]);
            tf32_split(pb[8 * 68],     ph[1], pl[1]);
            tf32_split(pb[4],          ph[2], pl[2]);
            tf32_split(pb[8 * 68 + 4], ph[3], pl[3]);
#pragma unroll
            for (int nt = 0; nt < 16; nt++) {
                const unsigned* vb  = Vh + (k0 + tig) * 136 + nt * 8 + gid;
                const unsigned* vlb = Vl + (k0 + tig) * 136 + nt * 8 + gid;
                unsigned bh[2] = { vb[0],  vb[4 * 136] };
                unsigned bl[2] = { vlb[0], vlb[4 * 136] };
                mma_tf32(accO[nt], ph, bh);
                mma_tf32(accO[nt], pl, bh);
                mma_tf32(accO[nt], ph, bl);
            }
        }
    }

    float inv0 = 1.0f / l0, inv1 = 1.0f / l1;
    float* Og = g_att + ((size_t)b * S_ + q0 + wm + gid) * D_ + h * HD_;
    float* Og8 = Og + 8 * D_;
#pragma unroll
    for (int nt = 0; nt < 16; nt++) {
        *(float2*)(Og + nt * 8 + 2 * tig) =
            make_float2(accO[nt][0] * inv0, accO[nt][1] * inv0);
        *(float2*)(Og8 + nt * 8 + 2 * tig) =
            make_float2(accO[nt][2] * inv1, accO[nt][3] * inv1);
    }
}

// ---------------- launch ------------------------------------------------------
extern "C" void kernel_launch(void* const* d_in, const int* in_sizes, int n_in,
                              void* d_out, int out_size)
{
    const float* query = (const float*)d_in[0];
    const float* key   = (const float*)d_in[1];
    const float* value = (const float*)d_in[2];
    const int*   mask  = (const int*)d_in[3];
    const float* wq    = (const float*)d_in[4];
    const float* wk    = (const float*)d_in[5];
    const float* wv    = (const float*)d_in[6];
    const float* wo    = (const float*)d_in[7];
    float* out = (float*)d_out;

    float *gA;
    unsigned *aH, *aL, *wH, *wL;
    cudaGetSymbolAddress((void**)&gA, g_att);
    cudaGetSymbolAddress((void**)&aH, g_actH);
    cudaGetSymbolAddress((void**)&aL, g_actL);
    cudaGetSymbolAddress((void**)&wH, g_wH);
    cudaGetSymbolAddress((void**)&wL, g_wL);

    cudaFuncSetAttribute(attn_tc_kernel,
                         cudaFuncAttributeMaxDynamicSharedMemorySize,
                         ATT_SMEM_BYTES);
    cudaFuncSetAttribute(gemm3_kernel,
                         cudaFuncAttributeMaxDynamicSharedMemorySize,
                         GEMM_SMEM_BYTES);

    const int NA4 = (int)(MK_ACT / 4);   // float4 count, activations
    const int NW4 = (int)(MK_W / 4);     // float4 count, weights
    dim3 sgA((NA4 + 255) / 256), sgW((NW4 + 255) / 256);

    // RoPE tables
    rope_tables_kernel<<<(S_ * 64 + 255) / 256, 256>>>();

    // Pre-split QKV activations + weights into hi/lo slots 0..2
    split_kernel<<<sgA, 256>>>((const float4*)query, (uint4*)(aH),
                               (uint4*)(aL), NA4);
    split_kernel<<<sgA, 256>>>((const float4*)key,   (uint4*)(aH + MK_ACT),
                               (uint4*)(aL + MK_ACT), NA4);
    split_kernel<<<sgA, 256>>>((const float4*)value, (uint4*)(aH + 2 * MK_ACT),
                               (uint4*)(aL + 2 * MK_ACT), NA4);
    split_kernel<<<sgW, 256>>>((const float4*)wq, (uint4*)(wH),
                               (uint4*)(wL), NW4);
    split_kernel<<<sgW, 256>>>((const float4*)wk, (uint4*)(wH + MK_W),
                               (uint4*)(wL + MK_W), NW4);
    split_kernel<<<sgW, 256>>>((const float4*)wv, (uint4*)(wH + 2 * MK_W),
                               (uint4*)(wL + 2 * MK_W), NW4);

    // Fused Q/K/V projections (head layout)
    dim3 pg3(D_ / 128, (B_ * S_) / 128, 3);
    gemm3_kernel<<<pg3, 256, GEMM_SMEM_BYTES>>>(aH, aL, wH, wL, nullptr, 1);

    // RoPE on Q and K (in place)
    rope_apply_kernel<<<(2 * B_ * H_ * S_ * 64) / 256, 256>>>();

    // Attention (tensor-core)
    attn_tc_kernel<<<dim3(S_ / 128, B_ * H_), 256, ATT_SMEM_BYTES>>>(mask);

    // Output projection: split attention output + wo into slot 0, then GEMM
    split_kernel<<<sgA, 256>>>((const float4*)gA, (uint4*)(aH),
                               (uint4*)(aL), NA4);
    split_kernel<<<sgW, 256>>>((const float4*)wo, (uint4*)(wH),
                               (uint4*)(wL), NW4);
    dim3 pg1(D_ / 128, (B_ * S_) / 128, 1);
    gemm3_kernel<<<pg1, 256, GEMM_SMEM_BYTES>>>(aH, aL, wH, wL, out, 0);
}

// round 13
// speedup vs baseline: 1.1191x; 1.1191x over previous
#include <cuda_runtime.h>
#include <math.h>

#define B_  2
#define S_  2048
#define D_  2048
#define H_  16
#define HD_ 128

#define MK_ACT ((size_t)4096 * 2048)
#define MK_W   ((size_t)2048 * 2048)

// ---------------- scratch (device globals: no allocation allowed) -------------
__device__ float g_Q[(size_t)B_ * H_ * S_ * HD_];   // [B,H,S,hd]
__device__ float g_K[(size_t)B_ * H_ * S_ * HD_];
__device__ float g_V[(size_t)B_ * H_ * S_ * HD_];
__device__ float g_att[(size_t)B_ * S_ * D_];       // [B,S,D] attention output
__device__ float g_cos[S_ * 64];
__device__ float g_sin[S_ * 64];
// fragment-packed tf32 hi/lo buffers (3 slots for QKV batching)
__device__ unsigned g_actH[3 * MK_ACT];
__device__ unsigned g_actL[3 * MK_ACT];
__device__ unsigned g_wH[3 * MK_W];
__device__ unsigned g_wL[3 * MK_W];

// ---------------- RoPE tables -------------------------------------------------
__global__ void rope_tables_kernel() {
    int idx = blockIdx.x * blockDim.x + threadIdx.x;
    if (idx >= S_ * 64) return;
    int s = idx >> 6, j = idx & 63;
    float invf = (float)(1.0 / pow(10000.0, (double)(2 * j) / 128.0));
    float ang_f = (float)s * invf;
    double ang = (double)ang_f;
    g_cos[idx] = (float)cos(ang);
    g_sin[idx] = (float)sin(ang);
}

__global__ void rope_apply_kernel() {
    int idx = blockIdx.x * blockDim.x + threadIdx.x;
    const int total = B_ * H_ * S_ * 64;
    float* T = (idx < total) ? g_Q : g_K;
    int p = (idx < total) ? idx : idx - total;
    int j = p & 63;
    int row = p >> 6;                // (b*H + h)*S + s
    int s = row & (S_ - 1);
    size_t base = (size_t)row * HD_ + j;
    float c  = g_cos[(s << 6) + j];
    float sn = g_sin[(s << 6) + j];
    float x0 = T[base];
    float x1 = T[base + 64];
    T[base]      = x0 * c - x1 * sn;
    T[base + 64] = x1 * c + x0 * sn;
}

// ---------------- helpers ------------------------------------------------------
__device__ __forceinline__ void tf32_split(float x, unsigned &h, unsigned &l) {
    asm("cvt.rna.tf32.f32 %0, %1;" : "=r"(h) : "f"(x));
    float lf = x - __uint_as_float(h);    // exact (tf32 subset of fp32)
    asm("cvt.rna.tf32.f32 %0, %1;" : "=r"(l) : "f"(lf));
}

__device__ __forceinline__ void mma_tf32(float* c, const unsigned* a, const unsigned* b) {
    asm volatile(
        "mma.sync.aligned.m16n8k8.row.col.f32.tf32.tf32.f32 "
        "{%0,%1,%2,%3}, {%4,%5,%6,%7}, {%8,%9}, {%0,%1,%2,%3};"
        : "+f"(c[0]), "+f"(c[1]), "+f"(c[2]), "+f"(c[3])
        : "r"(a[0]), "r"(a[1]), "r"(a[2]), "r"(a[3]), "r"(b[0]), "r"(b[1]));
}

__device__ __forceinline__ void cp16(unsigned dst, const void* src) {
    asm volatile("cp.async.cg.shared.global [%0], [%1], 16;" :: "r"(dst), "l"(src) : "memory");
}

// ---------------- fragment-pack kernels ----------------------------------------
// A (activations, 4096x2048): tiles 128(m) x 32(k). Block (tm*64 + c) holds 1024
// uint4 groups. Group gi = ((mt*4 + ks)*2 + wmg)*32 + lane, words in a-frag
// register order: (r,k), (r+8,k), (r,k+4), (r+8,k+4).
__global__ void __launch_bounds__(256) packA_kernel(
    const float* __restrict__ src, uint4* __restrict__ h4, uint4* __restrict__ l4)
{
    size_t g = (size_t)blockIdx.x * 256 + threadIdx.x;
    int gi = (int)(g & 1023);
    size_t blk = g >> 10;
    int c  = (int)(blk & 63);
    int tm = (int)(blk >> 6);
    int lane = gi & 31, wmg = (gi >> 5) & 1, ks = (gi >> 6) & 3, mt = gi >> 8;
    int gid = lane >> 2, tig = lane & 3;
    int row = tm * 128 + wmg * 64 + mt * 16 + gid;
    int k   = c * 32 + ks * 8 + tig;
    const float* p = src + (size_t)row * D_ + k;
    float x0 = p[0], x1 = p[8 * D_], x2 = p[4], x3 = p[8 * D_ + 4];
    unsigned h0,h1,h2,h3,l0,l1,l2,l3;
    tf32_split(x0,h0,l0); tf32_split(x1,h1,l1);
    tf32_split(x2,h2,l2); tf32_split(x3,h3,l3);
    h4[g] = make_uint4(h0,h1,h2,h3);
    l4[g] = make_uint4(l0,l1,l2,l3);
}

// W (weights, 2048x2048): tiles 128(n) x 32(k). Block (tn*64 + c), 1024 groups.
// Group gi = ((pp*4 + ks)*4 + gq)*32 + lane, words: b-frags for nt=2pp,2pp+1:
// (n,k), (n,k+4), (n+8,k), (n+8,k+4)  with n = gq*32 + pp*16 + gid.
__global__ void __launch_bounds__(256) packW_kernel(
    const float* __restrict__ src, uint4* __restrict__ h4, uint4* __restrict__ l4)
{
    size_t g = (size_t)blockIdx.x * 256 + threadIdx.x;
    int gi = (int)(g & 1023);
    size_t blk = g >> 10;
    int c  = (int)(blk & 63);
    int tn = (int)(blk >> 6);
    int lane = gi & 31, gq = (gi >> 5) & 3, ks = (gi >> 7) & 3, pp = gi >> 9;
    int gid = lane >> 2, tig = lane & 3;
    int n = tn * 128 + gq * 32 + pp * 16 + gid;
    int k = c * 32 + ks * 8 + tig;
    const float* p = src + (size_t)n * D_ + k;
    float x0 = p[0], x1 = p[4], x2 = p[8 * D_], x3 = p[8 * D_ + 4];
    unsigned h0,h1,h2,h3,l0,l1,l2,l3;
    tf32_split(x0,h0,l0); tf32_split(x1,h1,l1);
    tf32_split(x2,h2,l2); tf32_split(x3,h3,l3);
    h4[g] = make_uint4(h0,h1,h2,h3);
    l4[g] = make_uint4(l0,l1,l2,l3);
}

// ---------------- 3xTF32 GEMM, fragment-packed operands, all LDS.128 -----------
// C[m,n] = sum_k A[m,k]*W[n,k]. 128x128 tile, BK=32, 256 threads (8 warps 2x4,
// warp 64x32), 3-stage cp.async over dense 64KB stages.
#define STU4 4096                     // uint4 per stage (Ah|Al|Wh|Wl x 1024)
#define STB  (STU4 * 16)              // 65536 bytes
#define GEMM_SMEM_BYTES (3 * STB)     // 196608

__global__ void __launch_bounds__(256) gemm3_kernel(
    const unsigned* __restrict__ AhB, const unsigned* __restrict__ AlB,
    const unsigned* __restrict__ WhB, const unsigned* __restrict__ WlB,
    float* __restrict__ Cout, int mode)
{
    extern __shared__ uint4 smq[];
    unsigned smb = (unsigned)__cvta_generic_to_shared(smq);

    int z = blockIdx.z;
    int tid = threadIdx.x, lane = tid & 31, warp = tid >> 5;
    int wmg = warp & 1, gq = warp >> 1;
    int wm = wmg * 64, wn = gq * 32;
    int gid = lane >> 2, tig = lane & 3;
    int tm = blockIdx.y, tn = blockIdx.x;
    int m0 = tm * 128, n0 = tn * 128;

    // packed uint4 pointers for this block's tile-row / tile-col
    const uint4* Ahp = (const uint4*)AhB + ((size_t)z * MK_ACT >> 2) + ((size_t)tm * 64 << 10);
    const uint4* Alp = (const uint4*)AlB + ((size_t)z * MK_ACT >> 2) + ((size_t)tm * 64 << 10);
    const uint4* Whp = (const uint4*)WhB + ((size_t)z * MK_W >> 2) + ((size_t)tn * 64 << 10);
    const uint4* Wlp = (const uint4*)WlB + ((size_t)z * MK_W >> 2) + ((size_t)tn * 64 << 10);

    float acc[4][4][4];
#pragma unroll
    for (int mt = 0; mt < 4; mt++)
#pragma unroll
        for (int nt = 0; nt < 4; nt++)
#pragma unroll
            for (int e = 0; e < 4; e++) acc[mt][nt][e] = 0.f;

    const int NCHUNK = D_ / 32;          // 64

    auto issue = [&](int c, int st) {
        if (c < NCHUNK) {
            unsigned sb = smb + st * STB;
            size_t gb = (size_t)c << 10;
#pragma unroll
            for (int r = 0; r < 4; r++) {
                int idx = tid + 256 * r;
                cp16(sb + idx * 16,                 Ahp + gb + idx);
                cp16(sb + (1024 + idx) * 16,        Alp + gb + idx);
                cp16(sb + (2048 + idx) * 16,        Whp + gb + idx);
                cp16(sb + (3072 + idx) * 16,        Wlp + gb + idx);
            }
        }
        asm volatile("cp.async.commit_group;" ::: "memory");
    };

    issue(0, 0);
    issue(1, 1);

    for (int c = 0; c < NCHUNK; c++) {
        int st = c % 3;
        asm volatile("cp.async.wait_group 1;" ::: "memory");
        __syncthreads();
        issue(c + 2, (c + 2) % 3);

        const uint4* AsH = smq + st * STU4;
        const uint4* AsL = AsH + 1024;
        const uint4* WsH = AsL + 1024;
        const uint4* WsL = WsH + 1024;

#pragma unroll
        for (int ks = 0; ks < 4; ks++) {
            uint4 ah4[4], al4[4], wh4[2], wl4[2];
#pragma unroll
            for (int mt = 0; mt < 4; mt++) {
                int off = ((mt * 4 + ks) * 2 + wmg) * 32 + lane;
                ah4[mt] = AsH[off];
                al4[mt] = AsL[off];
            }
#pragma unroll
            for (int pp = 0; pp < 2; pp++) {
                int off = ((pp * 4 + ks) * 4 + gq) * 32 + lane;
                wh4[pp] = WsH[off];
                wl4[pp] = WsL[off];
            }
#pragma unroll
            for (int mt = 0; mt < 4; mt++)
#pragma unroll
                for (int pp = 0; pp < 2; pp++) {
                    unsigned bh0[2] = { wh4[pp].x, wh4[pp].y };
                    unsigned bh1[2] = { wh4[pp].z, wh4[pp].w };
                    unsigned bl0[2] = { wl4[pp].x, wl4[pp].y };
                    unsigned bl1[2] = { wl4[pp].z, wl4[pp].w };
                    const unsigned* a_h = (const unsigned*)&ah4[mt];
                    const unsigned* a_l = (const unsigned*)&al4[mt];
                    mma_tf32(acc[mt][2*pp],     a_h, bh0);
                    mma_tf32(acc[mt][2*pp],     a_h, bl0);
                    mma_tf32(acc[mt][2*pp],     a_l, bh0);
                    mma_tf32(acc[mt][2*pp+1],   a_h, bh1);
                    mma_tf32(acc[mt][2*pp+1],   a_h, bl1);
                    mma_tf32(acc[mt][2*pp+1],   a_l, bh1);
                }
        }
    }

    float* C = (mode == 0) ? Cout : (z == 0 ? g_Q : (z == 1 ? g_K : g_V));

#pragma unroll
    for (int mt = 0; mt < 4; mt++) {
#pragma unroll
        for (int nt = 0; nt < 4; nt++) {
            int m = m0 + wm + mt * 16 + gid;
            int n = n0 + wn + nt * 8 + 2 * tig;
            float2 v0 = make_float2(acc[mt][nt][0], acc[mt][nt][1]);
            float2 v1 = make_float2(acc[mt][nt][2], acc[mt][nt][3]);
            if (mode == 0) {
                *(float2*)&C[(size_t)m * D_ + n]       = v0;
                *(float2*)&C[(size_t)(m + 8) * D_ + n] = v1;
            } else {
                int h = n >> 7, d = n & 127;
                int b = m >> 11, s = m & (S_ - 1);
                *(float2*)&C[(((size_t)b * H_ + h) * S_ + s) * HD_ + d] = v0;
                int m8 = m + 8;
                int b8 = m8 >> 11, s8 = m8 & (S_ - 1);
                *(float2*)&C[(((size_t)b8 * H_ + h) * S_ + s8) * HD_ + d] = v1;
            }
        }
    }
}

// ---------------- 3xTF32 tensor-core flash attention ---------------------------
#define AOFF_KH 16896
#define AOFF_KL (16896 + 8448)
#define AOFF_P  16896
#define AOFF_VH 33792
#define AOFF_VL 42496
#define AOFF_FLAG 51200
#define ATT_SMEM_BYTES ((51200 + 8) * 4)

__global__ void __launch_bounds__(256) attn_tc_kernel(const int* __restrict__ mask)
{
    extern __shared__ float sm[];
    float*    Qs  = sm;
    unsigned* Kh  = (unsigned*)(sm + AOFF_KH);
    unsigned* Kl  = (unsigned*)(sm + AOFF_KL);
    unsigned* Vh  = (unsigned*)(sm + AOFF_VH);
    unsigned* Vl  = (unsigned*)(sm + AOFF_VL);
    float*    Ps  = sm + AOFF_P;
    int*    flagp = (int*)(sm + AOFF_FLAG);

    int bh = blockIdx.y;
    int b = bh >> 4, h = bh & 15;
    int q0 = blockIdx.x * 128;
    int tid = threadIdx.x;
    int lane = tid & 31;
    int warp = tid >> 5;
    int gid = lane >> 2, tig = lane & 3;
    int wm = warp * 16;
    const float scale = 0.08838834764831843f;   // 1/sqrt(128)

    const float* Qg = g_Q + (size_t)bh * S_ * HD_ + (size_t)q0 * HD_;
    const float* Kg = g_K + (size_t)bh * S_ * HD_;
    const float* Vg = g_V + (size_t)bh * S_ * HD_;
    const int*   Mg = mask + (size_t)b * S_ * S_ + (size_t)q0 * S_;

#pragma unroll
    for (int r = 0; r < 16; r++) {
        int idx = tid + 256 * r;
        int row = idx >> 5;
        int col = (idx & 31) << 2;
        float4 v = *(const float4*)(Qg + (size_t)row * HD_ + col);
        float* dst = Qs + row * 132 + col;
        dst[0] = v.x * scale; dst[1] = v.y * scale;
        dst[2] = v.z * scale; dst[3] = v.w * scale;
    }

    float m0 = -INFINITY, m1 = -INFINITY, l0 = 0.f, l1 = 0.f;
    float accO[16][4];
#pragma unroll
    for (int nt = 0; nt < 16; nt++)
#pragma unroll
        for (int e = 0; e < 4; e++) accO[nt][e] = 0.f;

    for (int kt = 0; kt < S_; kt += 64) {
        __syncthreads();
        bool ok = true;
#pragma unroll
        for (int r = 0; r < 8; r++) {
            int idx = tid + 256 * r;
            int row = idx >> 5;
            int col = (idx & 31) << 2;
            float4 kv = *(const float4*)(Kg + (size_t)(kt + row) * HD_ + col);
            unsigned h0,h1,h2,h3,l0_,l1_,l2_,l3_;
            tf32_split(kv.x, h0, l0_); tf32_split(kv.y, h1, l1_);
            tf32_split(kv.z, h2, l2_); tf32_split(kv.w, h3, l3_);
            *(uint4*)&Kh[row * 132 + col] = make_uint4(h0,h1,h2,h3);
            *(uint4*)&Kl[row * 132 + col] = make_uint4(l0_,l1_,l2_,l3_);
            float4 vv = *(const float4*)(Vg + (size_t)(kt + row) * HD_ + col);
            tf32_split(vv.x, h0, l0_); tf32_split(vv.y, h1, l1_);
            tf32_split(vv.z, h2, l2_); tf32_split(vv.w, h3, l3_);
            *(uint4*)&Vh[row * 136 + col] = make_uint4(h0,h1,h2,h3);
            *(uint4*)&Vl[row * 136 + col] = make_uint4(l0_,l1_,l2_,l3_);
        }
#pragma unroll
        for (int r = 0; r < 8; r++) {
            int idx = tid + 256 * r;
            int mrow = idx >> 4;
            int mc = (idx & 15) << 2;
            int4 mm = *(const int4*)(Mg + (size_t)mrow * S_ + kt + mc);
            ok = ok && (mm.x != 0) && (mm.y != 0) && (mm.z != 0) && (mm.w != 0);
        }
        unsigned bal = __ballot_sync(0xffffffffu, ok);
        if (lane == 0) flagp[warp] = (bal == 0xffffffffu) ? 1 : 0;
        __syncthreads();
        int allones = flagp[0] & flagp[1] & flagp[2] & flagp[3]
                    & flagp[4] & flagp[5] & flagp[6] & flagp[7];

        float sacc[8][4];
#pragma unroll
        for (int nt = 0; nt < 8; nt++)
#pragma unroll
            for (int e = 0; e < 4; e++) sacc[nt][e] = 0.f;

#pragma unroll
        for (int ks = 0; ks < 16; ks++) {
            int k0 = ks * 8;
            const float* qb = Qs + (wm + gid) * 132 + k0 + tig;
            unsigned ah[4], al[4];
            tf32_split(qb[0],          ah[0], al[0]);
            tf32_split(qb[8 * 132],    ah[1], al[1]);
            tf32_split(qb[4],          ah[2], al[2]);
            tf32_split(qb[8 * 132 + 4],ah[3], al[3]);
#pragma unroll
            for (int nt = 0; nt < 8; nt++) {
                const unsigned* kb  = Kh + (nt * 8 + gid) * 132 + k0 + tig;
                const unsigned* klb = Kl + (nt * 8 + gid) * 132 + k0 + tig;
                unsigned bh[2] = { kb[0], kb[4] };
                unsigned bl[2] = { klb[0], klb[4] };
                mma_tf32(sacc[nt], ah, bh);
                mma_tf32(sacc[nt], ah, bl);
                mma_tf32(sacc[nt], al, bh);
            }
        }

        if (!allones) {
            const int* M2 = mask + (size_t)b * S_ * S_;
#pragma unroll
            for (int nt = 0; nt < 8; nt++)
#pragma unroll
                for (int v = 0; v < 4; v++) {
                    int row = q0 + wm + gid + ((v >> 1) << 3);
                    int col = kt + nt * 8 + 2 * tig + (v & 1);
                    if (M2[(size_t)row * S_ + col] == 0) sacc[nt][v] = -1e30f;
                }
        }

        float mx0 = -INFINITY, mx1 = -INFINITY;
#pragma unroll
        for (int nt = 0; nt < 8; nt++) {
            mx0 = fmaxf(mx0, fmaxf(sacc[nt][0], sacc[nt][1]));
            mx1 = fmaxf(mx1, fmaxf(sacc[nt][2], sacc[nt][3]));
        }
        mx0 = fmaxf(mx0, __shfl_xor_sync(0xffffffffu, mx0, 1));
        mx0 = fmaxf(mx0, __shfl_xor_sync(0xffffffffu, mx0, 2));
        mx1 = fmaxf(mx1, __shfl_xor_sync(0xffffffffu, mx1, 1));
        mx1 = fmaxf(mx1, __shfl_xor_sync(0xffffffffu, mx1, 2));
        float mn0 = fmaxf(m0, mx0), mn1 = fmaxf(m1, mx1);
        float c0 = __expf(m0 - mn0), c1 = __expf(m1 - mn1);
        m0 = mn0; m1 = mn1;
        float s0 = 0.f, s1 = 0.f;
#pragma unroll
        for (int nt = 0; nt < 8; nt++) {
            sacc[nt][0] = __expf(sacc[nt][0] - mn0);
            sacc[nt][1] = __expf(sacc[nt][1] - mn0);
            sacc[nt][2] = __expf(sacc[nt][2] - mn1);
            sacc[nt][3] = __expf(sacc[nt][3] - mn1);
            s0 += sacc[nt][0] + sacc[nt][1];
            s1 += sacc[nt][2] + sacc[nt][3];
        }
        s0 += __shfl_xor_sync(0xffffffffu, s0, 1);
        s0 += __shfl_xor_sync(0xffffffffu, s0, 2);
        s1 += __shfl_xor_sync(0xffffffffu, s1, 1);
        s1 += __shfl_xor_sync(0xffffffffu, s1, 2);
        l0 = l0 * c0 + s0;
        l1 = l1 * c1 + s1;
#pragma unroll
        for (int nt = 0; nt < 16; nt++) {
            accO[nt][0] *= c0; accO[nt][1] *= c0;
            accO[nt][2] *= c1; accO[nt][3] *= c1;
        }

        __syncthreads();
#pragma unroll
        for (int nt = 0; nt < 8; nt++) {
            *(float2*)(Ps + (wm + gid) * 68 + nt * 8 + 2 * tig) =
                make_float2(sacc[nt][0], sacc[nt][1]);
            *(float2*)(Ps + (wm + 8 + gid) * 68 + nt * 8 + 2 * tig) =
                make_float2(sacc[nt][2], sacc[nt][3]);
        }
        __syncwarp();

#pragma unroll
        for (int ks = 0; ks < 8; ks++) {
            int k0 = ks * 8;
            const float* pb = Ps + (wm + gid) * 68 + k0 + tig;
            unsigned ph[4], pl[4];
            tf32_split(pb[0],          ph[0], pl[0]);
            tf32_split(pb[8 * 68],     ph[1], pl[1]);
            tf32_split(pb[4],          ph[2], pl[2]);
            tf32_split(pb[8 * 68 + 4], ph[3], pl[3]);
#pragma unroll
            for (int nt = 0; nt < 16; nt++) {
                const unsigned* vb  = Vh + (k0 + tig) * 136 + nt * 8 + gid;
                const unsigned* vlb = Vl + (k0 + tig) * 136 + nt * 8 + gid;
                unsigned bh[2] = { vb[0],  vb[4 * 136] };
                unsigned bl[2] = { vlb[0], vlb[4 * 136] };
                mma_tf32(accO[nt], ph, bh);
                mma_tf32(accO[nt], pl, bh);
                mma_tf32(accO[nt], ph, bl);
            }
        }
    }

    float inv0 = 1.0f / l0, inv1 = 1.0f / l1;
    float* Og = g_att + ((size_t)b * S_ + q0 + wm + gid) * D_ + h * HD_;
    float* Og8 = Og + 8 * D_;
#pragma unroll
    for (int nt = 0; nt < 16; nt++) {
        *(float2*)(Og + nt * 8 + 2 * tig) =
            make_float2(accO[nt][0] * inv0, accO[nt][1] * inv0);
        *(float2*)(Og8 + nt * 8 + 2 * tig) =
            make_float2(accO[nt][2] * inv1, accO[nt][3] * inv1);
    }
}

// ---------------- launch ------------------------------------------------------
extern "C" void kernel_launch(void* const* d_in, const int* in_sizes, int n_in,
                              void* d_out, int out_size)
{
    const float* query = (const float*)d_in[0];
    const float* key   = (const float*)d_in[1];
    const float* value = (const float*)d_in[2];
    const int*   mask  = (const int*)d_in[3];
    const float* wq    = (const float*)d_in[4];
    const float* wk    = (const float*)d_in[5];
    const float* wv    = (const float*)d_in[6];
    const float* wo    = (const float*)d_in[7];
    float* out = (float*)d_out;

    float *gA;
    unsigned *aH, *aL, *wH, *wL;
    cudaGetSymbolAddress((void**)&gA, g_att);
    cudaGetSymbolAddress((void**)&aH, g_actH);
    cudaGetSymbolAddress((void**)&aL, g_actL);
    cudaGetSymbolAddress((void**)&wH, g_wH);
    cudaGetSymbolAddress((void**)&wL, g_wL);

    cudaFuncSetAttribute(attn_tc_kernel,
                         cudaFuncAttributeMaxDynamicSharedMemorySize,
                         ATT_SMEM_BYTES);
    cudaFuncSetAttribute(gemm3_kernel,
                         cudaFuncAttributeMaxDynamicSharedMemorySize,
                         GEMM_SMEM_BYTES);

    const int NAG = (int)(MK_ACT / 4 / 256);   // packA blocks (8192)
    const int NWG = (int)(MK_W / 4 / 256);     // packW blocks (4096)

    // RoPE tables
    rope_tables_kernel<<<(S_ * 64 + 255) / 256, 256>>>();

    // Fragment-pack QKV activations + weights into slots 0..2
    packA_kernel<<<NAG, 256>>>(query, (uint4*)(aH), (uint4*)(aL));
    packA_kernel<<<NAG, 256>>>(key,   (uint4*)(aH + MK_ACT), (uint4*)(aL + MK_ACT));
    packA_kernel<<<NAG, 256>>>(value, (uint4*)(aH + 2 * MK_ACT), (uint4*)(aL + 2 * MK_ACT));
    packW_kernel<<<NWG, 256>>>(wq, (uint4*)(wH), (uint4*)(wL));
    packW_kernel<<<NWG, 256>>>(wk, (uint4*)(wH + MK_W), (uint4*)(wL + MK_W));
    packW_kernel<<<NWG, 256>>>(wv, (uint4*)(wH + 2 * MK_W), (uint4*)(wL + 2 * MK_W));

    // Fused Q/K/V projections (head layout)
    dim3 pg3(D_ / 128, (B_ * S_) / 128, 3);
    gemm3_kernel<<<pg3, 256, GEMM_SMEM_BYTES>>>(aH, aL, wH, wL, nullptr, 1);

    // RoPE on Q and K (in place)
    rope_apply_kernel<<<(2 * B_ * H_ * S_ * 64) / 256, 256>>>();

    // Attention (tensor-core)
    attn_tc_kernel<<<dim3(S_ / 128, B_ * H_), 256, ATT_SMEM_BYTES>>>(mask);

    // Output projection: pack attention output + wo into slot 0, then GEMM
    packA_kernel<<<NAG, 256>>>(gA, (uint4*)(aH), (uint4*)(aL));
    packW_kernel<<<NWG, 256>>>(wo, (uint4*)(wH), (uint4*)(wL));
    dim3 pg1(D_ / 128, (B_ * S_) / 128, 1);
    gemm3_kernel<<<pg1, 256, GEMM_SMEM_BYTES>>>(aH, aL, wH, wL, out, 0);
}

// round 14
// speedup vs baseline: 1.1615x; 1.0379x over previous
#include <cuda_runtime.h>
#include <math.h>

#define B_  2
#define S_  2048
#define D_  2048
#define H_  16
#define HD_ 128

#define MK_ACT ((size_t)4096 * 2048)
#define MK_W   ((size_t)2048 * 2048)

// ---------------- scratch (device globals: no allocation allowed) -------------
__device__ float g_Q[(size_t)B_ * H_ * S_ * HD_];   // [B,H,S,hd]
__device__ float g_K[(size_t)B_ * H_ * S_ * HD_];
__device__ float g_V[(size_t)B_ * H_ * S_ * HD_];
__device__ float g_att[(size_t)B_ * S_ * D_];       // [B,S,D] attention output
__device__ float g_cos[S_ * 64];
__device__ float g_sin[S_ * 64];
// fragment-packed tf32 hi/lo buffers (3 slots; slots 1,2 reused for packed K/V)
__device__ unsigned g_actH[3 * MK_ACT];
__device__ unsigned g_actL[3 * MK_ACT];
__device__ unsigned g_wH[3 * MK_W];
__device__ unsigned g_wL[3 * MK_W];

// ---------------- RoPE tables -------------------------------------------------
__global__ void rope_tables_kernel() {
    int idx = blockIdx.x * blockDim.x + threadIdx.x;
    if (idx >= S_ * 64) return;
    int s = idx >> 6, j = idx & 63;
    float invf = (float)(1.0 / pow(10000.0, (double)(2 * j) / 128.0));
    float ang_f = (float)s * invf;
    double ang = (double)ang_f;
    g_cos[idx] = (float)cos(ang);
    g_sin[idx] = (float)sin(ang);
}

__global__ void rope_apply_kernel() {
    int idx = blockIdx.x * blockDim.x + threadIdx.x;
    const int total = B_ * H_ * S_ * 64;
    float* T = (idx < total) ? g_Q : g_K;
    int p = (idx < total) ? idx : idx - total;
    int j = p & 63;
    int row = p >> 6;                // (b*H + h)*S + s
    int s = row & (S_ - 1);
    size_t base = (size_t)row * HD_ + j;
    float c  = g_cos[(s << 6) + j];
    float sn = g_sin[(s << 6) + j];
    float x0 = T[base];
    float x1 = T[base + 64];
    T[base]      = x0 * c - x1 * sn;
    T[base + 64] = x1 * c + x0 * sn;
}

// ---------------- helpers ------------------------------------------------------
__device__ __forceinline__ void tf32_split(float x, unsigned &h, unsigned &l) {
    asm("cvt.rna.tf32.f32 %0, %1;" : "=r"(h) : "f"(x));
    float lf = x - __uint_as_float(h);    // exact (tf32 subset of fp32)
    asm("cvt.rna.tf32.f32 %0, %1;" : "=r"(l) : "f"(lf));
}

__device__ __forceinline__ void mma_tf32(float* c, const unsigned* a, const unsigned* b) {
    asm volatile(
        "mma.sync.aligned.m16n8k8.row.col.f32.tf32.tf32.f32 "
        "{%0,%1,%2,%3}, {%4,%5,%6,%7}, {%8,%9}, {%0,%1,%2,%3};"
        : "+f"(c[0]), "+f"(c[1]), "+f"(c[2]), "+f"(c[3])
        : "r"(a[0]), "r"(a[1]), "r"(a[2]), "r"(a[3]), "r"(b[0]), "r"(b[1]));
}

__device__ __forceinline__ void cp16(unsigned dst, const void* src) {
    asm volatile("cp.async.cg.shared.global [%0], [%1], 16;" :: "r"(dst), "l"(src) : "memory");
}

// ---------------- fragment-pack kernels (GEMM operands) ------------------------
__global__ void __launch_bounds__(256) packA_kernel(
    const float* __restrict__ src, uint4* __restrict__ h4, uint4* __restrict__ l4)
{
    size_t g = (size_t)blockIdx.x * 256 + threadIdx.x;
    int gi = (int)(g & 1023);
    size_t blk = g >> 10;
    int c  = (int)(blk & 63);
    int tm = (int)(blk >> 6);
    int lane = gi & 31, wmg = (gi >> 5) & 1, ks = (gi >> 6) & 3, mt = gi >> 8;
    int gid = lane >> 2, tig = lane & 3;
    int row = tm * 128 + wmg * 64 + mt * 16 + gid;
    int k   = c * 32 + ks * 8 + tig;
    const float* p = src + (size_t)row * D_ + k;
    float x0 = p[0], x1 = p[8 * D_], x2 = p[4], x3 = p[8 * D_ + 4];
    unsigned h0,h1,h2,h3,l0,l1,l2,l3;
    tf32_split(x0,h0,l0); tf32_split(x1,h1,l1);
    tf32_split(x2,h2,l2); tf32_split(x3,h3,l3);
    h4[g] = make_uint4(h0,h1,h2,h3);
    l4[g] = make_uint4(l0,l1,l2,l3);
}

__global__ void __launch_bounds__(256) packW_kernel(
    const float* __restrict__ src, uint4* __restrict__ h4, uint4* __restrict__ l4)
{
    size_t g = (size_t)blockIdx.x * 256 + threadIdx.x;
    int gi = (int)(g & 1023);
    size_t blk = g >> 10;
    int c  = (int)(blk & 63);
    int tn = (int)(blk >> 6);
    int lane = gi & 31, gq = (gi >> 5) & 3, ks = (gi >> 7) & 3, pp = gi >> 9;
    int gid = lane >> 2, tig = lane & 3;
    int n = tn * 128 + gq * 32 + pp * 16 + gid;
    int k = c * 32 + ks * 8 + tig;
    const float* p = src + (size_t)n * D_ + k;
    float x0 = p[0], x1 = p[4], x2 = p[8 * D_], x3 = p[8 * D_ + 4];
    unsigned h0,h1,h2,h3,l0,l1,l2,l3;
    tf32_split(x0,h0,l0); tf32_split(x1,h1,l1);
    tf32_split(x2,h2,l2); tf32_split(x3,h3,l3);
    h4[g] = make_uint4(h0,h1,h2,h3);
    l4[g] = make_uint4(l0,l1,l2,l3);
}

// ---------------- fragment-pack kernels (attention K/V) ------------------------
// K packed per (bh, ktile of 64 keys): 2048 uint4. off = (ks*4+pp)*32+lane,
// ks in [0,16) (d chunks of 8), pp in [0,4) (key nt pairs).
// uint4 = { K[2pp*8+gid][ks*8+tig], K[..][+4], K[(2pp+1)*8+gid][..], K[..][+4] }
__global__ void __launch_bounds__(256) packK_kernel(
    const float* __restrict__ src, uint4* __restrict__ h4, uint4* __restrict__ l4)
{
    size_t g = (size_t)blockIdx.x * 256 + threadIdx.x;
    int off = (int)(g & 2047);
    int kt  = (int)((g >> 11) & 31);
    int bh  = (int)(g >> 16);
    int lane = off & 31, pp = (off >> 5) & 3, ks = off >> 7;
    int gid = lane >> 2, tig = lane & 3;
    const float* Kb = src + (((size_t)bh * S_) + kt * 64) * HD_;
    int n0 = 2 * pp * 8 + gid;
    int k  = ks * 8 + tig;
    float x0 = Kb[(size_t)n0 * HD_ + k];
    float x1 = Kb[(size_t)n0 * HD_ + k + 4];
    float x2 = Kb[(size_t)(n0 + 8) * HD_ + k];
    float x3 = Kb[(size_t)(n0 + 8) * HD_ + k + 4];
    unsigned h0,h1,h2,h3,l0,l1,l2,l3;
    tf32_split(x0,h0,l0); tf32_split(x1,h1,l1);
    tf32_split(x2,h2,l2); tf32_split(x3,h3,l3);
    h4[g] = make_uint4(h0,h1,h2,h3);
    l4[g] = make_uint4(l0,l1,l2,l3);
}

// V packed per (bh, ktile): off = (ks*8+pp)*32+lane, ks in [0,8) (key chunks),
// pp in [0,8) (d nt pairs).
// uint4 = { V[ks*8+tig][2pp*8+gid], V[+4][..], V[ks*8+tig][(2pp+1)*8+gid], V[+4][..] }
__global__ void __launch_bounds__(256) packV_kernel(
    const float* __restrict__ src, uint4* __restrict__ h4, uint4* __restrict__ l4)
{
    size_t g = (size_t)blockIdx.x * 256 + threadIdx.x;
    int off = (int)(g & 2047);
    int kt  = (int)((g >> 11) & 31);
    int bh  = (int)(g >> 16);
    int lane = off & 31, pp = (off >> 5) & 7, ks = off >> 8;
    int gid = lane >> 2, tig = lane & 3;
    const float* Vb = src + (((size_t)bh * S_) + kt * 64) * HD_;
    int kk = ks * 8 + tig;
    int d0 = 2 * pp * 8 + gid;
    float x0 = Vb[(size_t)kk * HD_ + d0];
    float x1 = Vb[(size_t)(kk + 4) * HD_ + d0];
    float x2 = Vb[(size_t)kk * HD_ + d0 + 8];
    float x3 = Vb[(size_t)(kk + 4) * HD_ + d0 + 8];
    unsigned h0,h1,h2,h3,l0,l1,l2,l3;
    tf32_split(x0,h0,l0); tf32_split(x1,h1,l1);
    tf32_split(x2,h2,l2); tf32_split(x3,h3,l3);
    h4[g] = make_uint4(h0,h1,h2,h3);
    l4[g] = make_uint4(l0,l1,l2,l3);
}

// ---------------- 3xTF32 GEMM (unchanged from R13 WIN) -------------------------
#define STU4 4096
#define STB  (STU4 * 16)
#define GEMM_SMEM_BYTES (3 * STB)

__global__ void __launch_bounds__(256) gemm3_kernel(
    const unsigned* __restrict__ AhB, const unsigned* __restrict__ AlB,
    const unsigned* __restrict__ WhB, const unsigned* __restrict__ WlB,
    float* __restrict__ Cout, int mode)
{
    extern __shared__ uint4 smq[];
    unsigned smb = (unsigned)__cvta_generic_to_shared(smq);

    int z = blockIdx.z;
    int tid = threadIdx.x, lane = tid & 31, warp = tid >> 5;
    int wmg = warp & 1, gq = warp >> 1;
    int wm = wmg * 64, wn = gq * 32;
    int gid = lane >> 2, tig = lane & 3;
    int tm = blockIdx.y, tn = blockIdx.x;
    int m0 = tm * 128, n0 = tn * 128;

    const uint4* Ahp = (const uint4*)AhB + ((size_t)z * MK_ACT >> 2) + ((size_t)tm * 64 << 10);
    const uint4* Alp = (const uint4*)AlB + ((size_t)z * MK_ACT >> 2) + ((size_t)tm * 64 << 10);
    const uint4* Whp = (const uint4*)WhB + ((size_t)z * MK_W >> 2) + ((size_t)tn * 64 << 10);
    const uint4* Wlp = (const uint4*)WlB + ((size_t)z * MK_W >> 2) + ((size_t)tn * 64 << 10);

    float acc[4][4][4];
#pragma unroll
    for (int mt = 0; mt < 4; mt++)
#pragma unroll
        for (int nt = 0; nt < 4; nt++)
#pragma unroll
            for (int e = 0; e < 4; e++) acc[mt][nt][e] = 0.f;

    const int NCHUNK = D_ / 32;

    auto issue = [&](int c, int st) {
        if (c < NCHUNK) {
            unsigned sb = smb + st * STB;
            size_t gb = (size_t)c << 10;
#pragma unroll
            for (int r = 0; r < 4; r++) {
                int idx = tid + 256 * r;
                cp16(sb + idx * 16,          Ahp + gb + idx);
                cp16(sb + (1024 + idx) * 16, Alp + gb + idx);
                cp16(sb + (2048 + idx) * 16, Whp + gb + idx);
                cp16(sb + (3072 + idx) * 16, Wlp + gb + idx);
            }
        }
        asm volatile("cp.async.commit_group;" ::: "memory");
    };

    issue(0, 0);
    issue(1, 1);

    for (int c = 0; c < NCHUNK; c++) {
        int st = c % 3;
        asm volatile("cp.async.wait_group 1;" ::: "memory");
        __syncthreads();
        issue(c + 2, (c + 2) % 3);

        const uint4* AsH = smq + st * STU4;
        const uint4* AsL = AsH + 1024;
        const uint4* WsH = AsL + 1024;
        const uint4* WsL = WsH + 1024;

#pragma unroll
        for (int ks = 0; ks < 4; ks++) {
            uint4 ah4[4], al4[4], wh4[2], wl4[2];
#pragma unroll
            for (int mt = 0; mt < 4; mt++) {
                int off = ((mt * 4 + ks) * 2 + wmg) * 32 + lane;
                ah4[mt] = AsH[off];
                al4[mt] = AsL[off];
            }
#pragma unroll
            for (int pp = 0; pp < 2; pp++) {
                int off = ((pp * 4 + ks) * 4 + gq) * 32 + lane;
                wh4[pp] = WsH[off];
                wl4[pp] = WsL[off];
            }
#pragma unroll
            for (int mt = 0; mt < 4; mt++)
#pragma unroll
                for (int pp = 0; pp < 2; pp++) {
                    unsigned bh0[2] = { wh4[pp].x, wh4[pp].y };
                    unsigned bh1[2] = { wh4[pp].z, wh4[pp].w };
                    unsigned bl0[2] = { wl4[pp].x, wl4[pp].y };
                    unsigned bl1[2] = { wl4[pp].z, wl4[pp].w };
                    const unsigned* a_h = (const unsigned*)&ah4[mt];
                    const unsigned* a_l = (const unsigned*)&al4[mt];
                    mma_tf32(acc[mt][2*pp],   a_h, bh0);
                    mma_tf32(acc[mt][2*pp],   a_h, bl0);
                    mma_tf32(acc[mt][2*pp],   a_l, bh0);
                    mma_tf32(acc[mt][2*pp+1], a_h, bh1);
                    mma_tf32(acc[mt][2*pp+1], a_h, bl1);
                    mma_tf32(acc[mt][2*pp+1], a_l, bh1);
                }
        }
    }

    float* C = (mode == 0) ? Cout : (z == 0 ? g_Q : (z == 1 ? g_K : g_V));

#pragma unroll
    for (int mt = 0; mt < 4; mt++) {
#pragma unroll
        for (int nt = 0; nt < 4; nt++) {
            int m = m0 + wm + mt * 16 + gid;
            int n = n0 + wn + nt * 8 + 2 * tig;
            float2 v0 = make_float2(acc[mt][nt][0], acc[mt][nt][1]);
            float2 v1 = make_float2(acc[mt][nt][2], acc[mt][nt][3]);
            if (mode == 0) {
                *(float2*)&C[(size_t)m * D_ + n]       = v0;
                *(float2*)&C[(size_t)(m + 8) * D_ + n] = v1;
            } else {
                int h = n >> 7, d = n & 127;
                int b = m >> 11, s = m & (S_ - 1);
                *(float2*)&C[(((size_t)b * H_ + h) * S_ + s) * HD_ + d] = v0;
                int m8 = m + 8;
                int b8 = m8 >> 11, s8 = m8 & (S_ - 1);
                *(float2*)&C[(((size_t)b8 * H_ + h) * S_ + s8) * HD_ + d] = v1;
            }
        }
    }
}

// ---------------- attention v2: packed K/V, cp.async pipeline, shfl-P ----------
// smem (float words): Qs fp32 128x132 @0 (16896) | KpH @16896 (8192) |
// KpL @25088 | VpH @33280 | VpL @41472 | flags @49664 (8)
#define ATT_SMEM_BYTES ((49664 + 8) * 4)

__global__ void __launch_bounds__(256) attn_tc2_kernel(
    const int* __restrict__ mask,
    const uint4* __restrict__ kHg, const uint4* __restrict__ kLg,
    const uint4* __restrict__ vHg, const uint4* __restrict__ vLg)
{
    extern __shared__ float sm[];
    float* Qs  = sm;
    uint4* KpH = (uint4*)(sm + 16896);
    uint4* KpL = KpH + 2048;
    uint4* VpH = (uint4*)(sm + 33280);
    uint4* VpL = VpH + 2048;
    int* flagp = (int*)(sm + 49664);
    unsigned smk = (unsigned)__cvta_generic_to_shared(KpH);
    unsigned smv = (unsigned)__cvta_generic_to_shared(VpH);

    int bh = blockIdx.y;
    int b = bh >> 4, h = bh & 15;
    int q0 = blockIdx.x * 128;
    int tid = threadIdx.x;
    int lane = tid & 31;
    int warp = tid >> 5;
    int gid = lane >> 2, tig = lane & 3;
    int wm = warp * 16;
    const float scale = 0.08838834764831843f;   // 1/sqrt(128)

    const float* Qg = g_Q + (size_t)bh * S_ * HD_ + (size_t)q0 * HD_;
    const int*   Mg = mask + (size_t)b * S_ * S_ + (size_t)q0 * S_;
    const uint4* kH = kHg + (size_t)bh * 65536;   // 32 tiles x 2048
    const uint4* kL = kLg + (size_t)bh * 65536;
    const uint4* vH = vHg + (size_t)bh * 65536;
    const uint4* vL = vLg + (size_t)bh * 65536;

    auto issueK = [&](int t) {
        if (t < 32) {
            size_t base = (size_t)t * 2048;
#pragma unroll
            for (int r = 0; r < 8; r++) {
                int idx = tid + 256 * r;
                cp16(smk + idx * 16,         kH + base + idx);
                cp16(smk + 32768 + idx * 16, kL + base + idx);
            }
        }
        asm volatile("cp.async.commit_group;" ::: "memory");
    };
    auto issueV = [&](int t) {
        if (t < 32) {
            size_t base = (size_t)t * 2048;
#pragma unroll
            for (int r = 0; r < 8; r++) {
                int idx = tid + 256 * r;
                cp16(smv + idx * 16,         vH + base + idx);
                cp16(smv + 32768 + idx * 16, vL + base + idx);
            }
        }
        asm volatile("cp.async.commit_group;" ::: "memory");
    };

    issueK(0);
    issueV(0);

    // Load Q tile (pre-scaled fp32), stride 132.
#pragma unroll
    for (int r = 0; r < 16; r++) {
        int idx = tid + 256 * r;
        int row = idx >> 5;
        int col = (idx & 31) << 2;
        float4 v = *(const float4*)(Qg + (size_t)row * HD_ + col);
        float* dst = Qs + row * 132 + col;
        dst[0] = v.x * scale; dst[1] = v.y * scale;
        dst[2] = v.z * scale; dst[3] = v.w * scale;
    }

    float m0 = -INFINITY, m1 = -INFINITY, l0 = 0.f, l1 = 0.f;
    float accO[16][4];
#pragma unroll
    for (int nt = 0; nt < 16; nt++)
#pragma unroll
        for (int e = 0; e < 4; e++) accO[nt][e] = 0.f;

    for (int t = 0; t < 32; t++) {
        int kt = t * 64;
        asm volatile("cp.async.wait_group 1;" ::: "memory");   // K(t) ready
        __syncthreads();

        // mask tile scan (flag published at next barrier)
        bool ok = true;
#pragma unroll
        for (int r = 0; r < 8; r++) {
            int idx = tid + 256 * r;
            int mrow = idx >> 4;
            int mc = (idx & 15) << 2;
            int4 mm = *(const int4*)(Mg + (size_t)mrow * S_ + kt + mc);
            ok = ok && (mm.x != 0) && (mm.y != 0) && (mm.z != 0) && (mm.w != 0);
        }
        unsigned bal = __ballot_sync(0xffffffffu, ok);
        if (lane == 0) flagp[warp] = (bal == 0xffffffffu) ? 1 : 0;

        // ---- S = (Q*scale) K^T  (16x64 per warp) ----
        float sacc[8][4];
#pragma unroll
        for (int nt = 0; nt < 8; nt++)
#pragma unroll
            for (int e = 0; e < 4; e++) sacc[nt][e] = 0.f;

#pragma unroll
        for (int ks = 0; ks < 16; ks++) {
            const float* qb = Qs + (wm + gid) * 132 + ks * 8 + tig;
            unsigned ah[4], al[4];
            tf32_split(qb[0],           ah[0], al[0]);
            tf32_split(qb[8 * 132],     ah[1], al[1]);
            tf32_split(qb[4],           ah[2], al[2]);
            tf32_split(qb[8 * 132 + 4], ah[3], al[3]);
#pragma unroll
            for (int pp = 0; pp < 4; pp++) {
                uint4 kh4 = KpH[(ks * 4 + pp) * 32 + lane];
                uint4 kl4 = KpL[(ks * 4 + pp) * 32 + lane];
                unsigned bh0[2] = { kh4.x, kh4.y };
                unsigned bh1[2] = { kh4.z, kh4.w };
                unsigned bl0[2] = { kl4.x, kl4.y };
                unsigned bl1[2] = { kl4.z, kl4.w };
                mma_tf32(sacc[2*pp],   ah, bh0);
                mma_tf32(sacc[2*pp],   ah, bl0);
                mma_tf32(sacc[2*pp],   al, bh0);
                mma_tf32(sacc[2*pp+1], ah, bh1);
                mma_tf32(sacc[2*pp+1], ah, bl1);
                mma_tf32(sacc[2*pp+1], al, bh1);
            }
        }
        __syncthreads();             // Kp reads done; flags visible

        int allones = flagp[0] & flagp[1] & flagp[2] & flagp[3]
                    & flagp[4] & flagp[5] & flagp[6] & flagp[7];
        if (!allones) {
            const int* M2 = mask + (size_t)b * S_ * S_;
#pragma unroll
            for (int nt = 0; nt < 8; nt++)
#pragma unroll
                for (int v = 0; v < 4; v++) {
                    int row = q0 + wm + gid + ((v >> 1) << 3);
                    int col = kt + nt * 8 + 2 * tig + (v & 1);
                    if (M2[(size_t)row * S_ + col] == 0) sacc[nt][v] = -1e30f;
                }
        }

        // ---- online softmax (warp-private) ----
        float mx0 = -INFINITY, mx1 = -INFINITY;
#pragma unroll
        for (int nt = 0; nt < 8; nt++) {
            mx0 = fmaxf(mx0, fmaxf(sacc[nt][0], sacc[nt][1]));
            mx1 = fmaxf(mx1, fmaxf(sacc[nt][2], sacc[nt][3]));
        }
        mx0 = fmaxf(mx0, __shfl_xor_sync(0xffffffffu, mx0, 1));
        mx0 = fmaxf(mx0, __shfl_xor_sync(0xffffffffu, mx0, 2));
        mx1 = fmaxf(mx1, __shfl_xor_sync(0xffffffffu, mx1, 1));
        mx1 = fmaxf(mx1, __shfl_xor_sync(0xffffffffu, mx1, 2));
        float mn0 = fmaxf(m0, mx0), mn1 = fmaxf(m1, mx1);
        float c0 = __expf(m0 - mn0), c1 = __expf(m1 - mn1);
        m0 = mn0; m1 = mn1;
        float s0 = 0.f, s1 = 0.f;
#pragma unroll
        for (int nt = 0; nt < 8; nt++) {
            sacc[nt][0] = __expf(sacc[nt][0] - mn0);
            sacc[nt][1] = __expf(sacc[nt][1] - mn0);
            sacc[nt][2] = __expf(sacc[nt][2] - mn1);
            sacc[nt][3] = __expf(sacc[nt][3] - mn1);
            s0 += sacc[nt][0] + sacc[nt][1];
            s1 += sacc[nt][2] + sacc[nt][3];
        }
        s0 += __shfl_xor_sync(0xffffffffu, s0, 1);
        s0 += __shfl_xor_sync(0xffffffffu, s0, 2);
        s1 += __shfl_xor_sync(0xffffffffu, s1, 1);
        s1 += __shfl_xor_sync(0xffffffffu, s1, 2);
        l0 = l0 * c0 + s0;
        l1 = l1 * c1 + s1;
#pragma unroll
        for (int nt = 0; nt < 16; nt++) {
            accO[nt][0] *= c0; accO[nt][1] *= c0;
            accO[nt][2] *= c1; accO[nt][3] *= c1;
        }

        issueK(t + 1);                                   // overlap with PV

        asm volatile("cp.async.wait_group 1;" ::: "memory");   // V(t) ready
        __syncthreads();

        // ---- O += P V  (16x128 per warp), P via shfl transpose ----
        int src0 = (gid << 2) | (tig >> 1);
        int src2 = src0 + 2;
        bool odd = (tig & 1) != 0;
#pragma unroll
        for (int ks = 0; ks < 8; ks++) {
            float s00 = __shfl_sync(0xffffffffu, sacc[ks][0], src0);
            float s01 = __shfl_sync(0xffffffffu, sacc[ks][1], src0);
            float s02 = __shfl_sync(0xffffffffu, sacc[ks][2], src0);
            float s03 = __shfl_sync(0xffffffffu, sacc[ks][3], src0);
            float s10 = __shfl_sync(0xffffffffu, sacc[ks][0], src2);
            float s11 = __shfl_sync(0xffffffffu, sacc[ks][1], src2);
            float s12 = __shfl_sync(0xffffffffu, sacc[ks][2], src2);
            float s13 = __shfl_sync(0xffffffffu, sacc[ks][3], src2);
            float p0 = odd ? s01 : s00;    // P[gid][ks*8+tig]
            float p1 = odd ? s03 : s02;    // P[gid+8][ks*8+tig]
            float p2 = odd ? s11 : s10;    // P[gid][ks*8+tig+4]
            float p3 = odd ? s13 : s12;    // P[gid+8][ks*8+tig+4]
            unsigned ph[4], pl[4];
            tf32_split(p0, ph[0], pl[0]);
            tf32_split(p1, ph[1], pl[1]);
            tf32_split(p2, ph[2], pl[2]);
            tf32_split(p3, ph[3], pl[3]);
#pragma unroll
            for (int pp = 0; pp < 8; pp++) {
                uint4 vh4 = VpH[(ks * 8 + pp) * 32 + lane];
                uint4 vl4 = VpL[(ks * 8 + pp) * 32 + lane];
                unsigned bh0[2] = { vh4.x, vh4.y };
                unsigned bh1[2] = { vh4.z, vh4.w };
                unsigned bl0[2] = { vl4.x, vl4.y };
                unsigned bl1[2] = { vl4.z, vl4.w };
                mma_tf32(accO[2*pp],   ph, bh0);
                mma_tf32(accO[2*pp],   pl, bh0);
                mma_tf32(accO[2*pp],   ph, bl0);
                mma_tf32(accO[2*pp+1], ph, bh1);
                mma_tf32(accO[2*pp+1], pl, bh1);
                mma_tf32(accO[2*pp+1], ph, bl1);
            }
        }
        __syncthreads();             // Vp reads done

        issueV(t + 1);
    }

    float inv0 = 1.0f / l0, inv1 = 1.0f / l1;
    float* Og = g_att + ((size_t)b * S_ + q0 + wm + gid) * D_ + h * HD_;
    float* Og8 = Og + 8 * D_;
#pragma unroll
    for (int nt = 0; nt < 16; nt++) {
        *(float2*)(Og + nt * 8 + 2 * tig) =
            make_float2(accO[nt][0] * inv0, accO[nt][1] * inv0);
        *(float2*)(Og8 + nt * 8 + 2 * tig) =
            make_float2(accO[nt][2] * inv1, accO[nt][3] * inv1);
    }
}

// ---------------- launch ------------------------------------------------------
extern "C" void kernel_launch(void* const* d_in, const int* in_sizes, int n_in,
                              void* d_out, int out_size)
{
    const float* query = (const float*)d_in[0];
    const float* key   = (const float*)d_in[1];
    const float* value = (const float*)d_in[2];
    const int*   mask  = (const int*)d_in[3];
    const float* wq    = (const float*)d_in[4];
    const float* wk    = (const float*)d_in[5];
    const float* wv    = (const float*)d_in[6];
    const float* wo    = (const float*)d_in[7];
    float* out = (float*)d_out;

    float *gA, *gK, *gV;
    unsigned *aH, *aL, *wH, *wL;
    cudaGetSymbolAddress((void**)&gA, g_att);
    cudaGetSymbolAddress((void**)&gK, g_K);
    cudaGetSymbolAddress((void**)&gV, g_V);
    cudaGetSymbolAddress((void**)&aH, g_actH);
    cudaGetSymbolAddress((void**)&aL, g_actL);
    cudaGetSymbolAddress((void**)&wH, g_wH);
    cudaGetSymbolAddress((void**)&wL, g_wL);

    cudaFuncSetAttribute(attn_tc2_kernel,
                         cudaFuncAttributeMaxDynamicSharedMemorySize,
                         ATT_SMEM_BYTES);
    cudaFuncSetAttribute(gemm3_kernel,
                         cudaFuncAttributeMaxDynamicSharedMemorySize,
                         GEMM_SMEM_BYTES);

    const int NAG = (int)(MK_ACT / 4 / 256);   // 8192
    const int NWG = (int)(MK_W / 4 / 256);     // 4096
    const int NKV = (int)((size_t)B_ * H_ * S_ * HD_ / 4 / 256);  // 8192

    // RoPE tables
    rope_tables_kernel<<<(S_ * 64 + 255) / 256, 256>>>();

    // Fragment-pack QKV activations + weights into slots 0..2
    packA_kernel<<<NAG, 256>>>(query, (uint4*)(aH), (uint4*)(aL));
    packA_kernel<<<NAG, 256>>>(key,   (uint4*)(aH + MK_ACT), (uint4*)(aL + MK_ACT));
    packA_kernel<<<NAG, 256>>>(value, (uint4*)(aH + 2 * MK_ACT), (uint4*)(aL + 2 * MK_ACT));
    packW_kernel<<<NWG, 256>>>(wq, (uint4*)(wH), (uint4*)(wL));
    packW_kernel<<<NWG, 256>>>(wk, (uint4*)(wH + MK_W), (uint4*)(wL + MK_W));
    packW_kernel<<<NWG, 256>>>(wv, (uint4*)(wH + 2 * MK_W), (uint4*)(wL + 2 * MK_W));

    // Fused Q/K/V projections (head layout)
    dim3 pg3(D_ / 128, (B_ * S_) / 128, 3);
    gemm3_kernel<<<pg3, 256, GEMM_SMEM_BYTES>>>(aH, aL, wH, wL, nullptr, 1);

    // RoPE on Q and K (in place)
    rope_apply_kernel<<<(2 * B_ * H_ * S_ * 64) / 256, 256>>>();

    // Pack roped K and V into attention fragment layout (reuse act slots 1,2)
    uint4* kHp = (uint4*)(aH + MK_ACT);
    uint4* kLp = (uint4*)(aL + MK_ACT);
    uint4* vHp = (uint4*)(aH + 2 * MK_ACT);
    uint4* vLp = (uint4*)(aL + 2 * MK_ACT);
    packK_kernel<<<NKV, 256>>>(gK, kHp, kLp);
    packV_kernel<<<NKV, 256>>>(gV, vHp, vLp);

    // Attention (packed, pipelined)
    attn_tc2_kernel<<<dim3(S_ / 128, B_ * H_), 256, ATT_SMEM_BYTES>>>(
        mask, kHp, kLp, vHp, vLp);

    // Output projection: pack attention output + wo into slot 0, then GEMM
    packA_kernel<<<NAG, 256>>>(gA, (uint4*)(aH), (uint4*)(aL));
    packW_kernel<<<NWG, 256>>>(wo, (uint4*)(wH), (uint4*)(wL));
    dim3 pg1(D_ / 128, (B_ * S_) / 128, 1);
    gemm3_kernel<<<pg1, 256, GEMM_SMEM_BYTES>>>(aH, aL, wH, wL, out, 0);
}

// round 15
// speedup vs baseline: 2.1417x; 1.8439x over previous
#include <cuda_runtime.h>
#include <cuda_bf16.h>
#include <math.h>

#define B_  2
#define S_  2048
#define D_  2048
#define H_  16
#define HD_ 128

#define MK_ACT ((size_t)4096 * 2048)
#define MK_W   ((size_t)2048 * 2048)
#define A_SLOT_U4 (MK_ACT / 8)        // uint4 per activation slot (bf16 h or l)
#define W_SLOT_U4 (MK_W / 8)

// ---------------- scratch (device globals: no allocation allowed) -------------
__device__ float g_Q[(size_t)B_ * H_ * S_ * HD_];   // [B,H,S,hd]
__device__ float g_K[(size_t)B_ * H_ * S_ * HD_];
__device__ float g_V[(size_t)B_ * H_ * S_ * HD_];
__device__ float g_att[(size_t)B_ * S_ * D_];       // [B,S,D]
__device__ float g_cos[S_ * 64];
__device__ float g_sin[S_ * 64];
// fragment-packed bf16 hi/lo buffers (3 slots; slots 1,2 reused for packed K/V)
__device__ unsigned g_actH[3 * (MK_ACT / 2)];
__device__ unsigned g_actL[3 * (MK_ACT / 2)];
__device__ unsigned g_wH[3 * (MK_W / 2)];
__device__ unsigned g_wL[3 * (MK_W / 2)];

// ---------------- RoPE tables -------------------------------------------------
__global__ void rope_tables_kernel() {
    int idx = blockIdx.x * blockDim.x + threadIdx.x;
    if (idx >= S_ * 64) return;
    int s = idx >> 6, j = idx & 63;
    float invf = (float)(1.0 / pow(10000.0, (double)(2 * j) / 128.0));
    float ang_f = (float)s * invf;
    double ang = (double)ang_f;
    g_cos[idx] = (float)cos(ang);
    g_sin[idx] = (float)sin(ang);
}

__global__ void rope_apply_kernel() {
    int idx = blockIdx.x * blockDim.x + threadIdx.x;
    const int total = B_ * H_ * S_ * 64;
    float* T = (idx < total) ? g_Q : g_K;
    int p = (idx < total) ? idx : idx - total;
    int j = p & 63;
    int row = p >> 6;
    int s = row & (S_ - 1);
    size_t base = (size_t)row * HD_ + j;
    float c  = g_cos[(s << 6) + j];
    float sn = g_sin[(s << 6) + j];
    float x0 = T[base];
    float x1 = T[base + 64];
    T[base]      = x0 * c - x1 * sn;
    T[base + 64] = x1 * c + x0 * sn;
}

// ---------------- helpers ------------------------------------------------------
// bf16 hi/lo split of two floats, packed into bf16x2 words (low half = first).
__device__ __forceinline__ void bf16_split2(float x0, float x1,
                                            unsigned &h2, unsigned &l2) {
    __nv_bfloat162 h = __floats2bfloat162_rn(x0, x1);
    float r0 = x0 - __bfloat162float(__low2bfloat16(h));
    float r1 = x1 - __bfloat162float(__high2bfloat16(h));
    __nv_bfloat162 l = __floats2bfloat162_rn(r0, r1);
    h2 = *reinterpret_cast<unsigned*>(&h);
    l2 = *reinterpret_cast<unsigned*>(&l);
}

__device__ __forceinline__ void mma_bf16(float* c, const unsigned* a, const unsigned* b) {
    asm volatile(
        "mma.sync.aligned.m16n8k16.row.col.f32.bf16.bf16.f32 "
        "{%0,%1,%2,%3}, {%4,%5,%6,%7}, {%8,%9}, {%0,%1,%2,%3};"
        : "+f"(c[0]), "+f"(c[1]), "+f"(c[2]), "+f"(c[3])
        : "r"(a[0]), "r"(a[1]), "r"(a[2]), "r"(a[3]), "r"(b[0]), "r"(b[1]));
}

__device__ __forceinline__ void cp16(unsigned dst, const void* src) {
    asm volatile("cp.async.cg.shared.global [%0], [%1], 16;" :: "r"(dst), "l"(src) : "memory");
}

__device__ __forceinline__ uint4 pack4(float2 v0, float2 v1, float2 v2, float2 v3,
                                       uint4 &lo) {
    uint4 hi;
    bf16_split2(v0.x, v0.y, hi.x, lo.x);
    bf16_split2(v1.x, v1.y, hi.y, lo.y);
    bf16_split2(v2.x, v2.y, hi.z, lo.z);
    bf16_split2(v3.x, v3.y, hi.w, lo.w);
    return hi;
}

// ---------------- fragment-pack kernels (GEMM operands, bf16) ------------------
// A: tiles 128(m) x 64(k); per (tm,c): 1024 uint4. gi = ((mt*4+ks)*2+wmg)*32+lane
// uint4 regs (a-frag m16n8k16): (row,k|k+1),(row+8,..),(row,k+8|k+9),(row+8,..)
__global__ void __launch_bounds__(256) packA_kernel(
    const float* __restrict__ src, uint4* __restrict__ h4, uint4* __restrict__ l4)
{
    size_t g = (size_t)blockIdx.x * 256 + threadIdx.x;
    int gi = (int)(g & 1023);
    size_t blk = g >> 10;
    int c  = (int)(blk & 31);
    int tm = (int)(blk >> 5);
    int lane = gi & 31, wmg = (gi >> 5) & 1, ks = (gi >> 6) & 3, mt = gi >> 8;
    int gid = lane >> 2, tig = lane & 3;
    int row = tm * 128 + wmg * 64 + mt * 16 + gid;
    int k   = c * 64 + ks * 16 + 2 * tig;
    const float* p = src + (size_t)row * D_ + k;
    uint4 lo;
    uint4 hi = pack4(*(const float2*)p, *(const float2*)(p + 8 * D_),
                     *(const float2*)(p + 8), *(const float2*)(p + 8 * D_ + 8), lo);
    h4[g] = hi; l4[g] = lo;
}

// W: tiles 128(n) x 64(k); gi = ((pp*4+ks)*4+gq)*32+lane
// uint4: b0(nt=2pp)=(n,k|k+1), b1(2pp)=(n,k+8|k+9), b0(2pp+1)=(n+8,..), b1(2pp+1)
__global__ void __launch_bounds__(256) packW_kernel(
    const float* __restrict__ src, uint4* __restrict__ h4, uint4* __restrict__ l4)
{
    size_t g = (size_t)blockIdx.x * 256 + threadIdx.x;
    int gi = (int)(g & 1023);
    size_t blk = g >> 10;
    int c  = (int)(blk & 31);
    int tn = (int)(blk >> 5);
    int lane = gi & 31, gq = (gi >> 5) & 3, ks = (gi >> 7) & 3, pp = gi >> 9;
    int gid = lane >> 2, tig = lane & 3;
    int n = tn * 128 + gq * 32 + pp * 16 + gid;
    int k = c * 64 + ks * 16 + 2 * tig;
    const float* p = src + (size_t)n * D_ + k;
    uint4 lo;
    uint4 hi = pack4(*(const float2*)p, *(const float2*)(p + 8),
                     *(const float2*)(p + 8 * D_), *(const float2*)(p + 8 * D_ + 8), lo);
    h4[g] = hi; l4[g] = lo;
}

// K (attention B of QK): per (bh,ktile): 1024 uint4. off = (ks*4+pp)*32+lane,
// ks=d chunk [0,8), pp=key pair [0,4).
// uint4: (key, d|d+1), (key, d+8|d+9), (key+8, d|d+1), (key+8, d+8|d+9)
__global__ void __launch_bounds__(256) packK_kernel(
    const float* __restrict__ src, uint4* __restrict__ h4, uint4* __restrict__ l4)
{
    size_t g = (size_t)blockIdx.x * 256 + threadIdx.x;
    int off = (int)(g & 1023);
    int kt  = (int)((g >> 10) & 31);
    int bh  = (int)(g >> 15);
    int lane = off & 31, pp = (off >> 5) & 3, ks = off >> 7;
    int gid = lane >> 2, tig = lane & 3;
    const float* Kb = src + (((size_t)bh * S_) + kt * 64) * HD_;
    int key = pp * 16 + gid;
    int d   = ks * 16 + 2 * tig;
    const float* p = Kb + (size_t)key * HD_ + d;
    uint4 lo;
    uint4 hi = pack4(*(const float2*)p, *(const float2*)(p + 8),
                     *(const float2*)(p + 8 * HD_), *(const float2*)(p + 8 * HD_ + 8), lo);
    h4[g] = hi; l4[g] = lo;
}

// V (attention B of PV): per (bh,ktile): 1024 uint4. off = (ks2*8+pp)*32+lane,
// ks2=key chunk [0,4), pp=d pair [0,8).
// uint4: pack(V[k0][d],V[k0+1][d]), pack(V[k0+8][d],V[k0+9][d]),
//        pack(V[k0][d+8],V[k0+1][d+8]), pack(V[k0+8][d+8],V[k0+9][d+8])
__global__ void __launch_bounds__(256) packV_kernel(
    const float* __restrict__ src, uint4* __restrict__ h4, uint4* __restrict__ l4)
{
    size_t g = (size_t)blockIdx.x * 256 + threadIdx.x;
    int off = (int)(g & 1023);
    int kt  = (int)((g >> 10) & 31);
    int bh  = (int)(g >> 15);
    int lane = off & 31, pp = (off >> 5) & 7, ks2 = off >> 8;
    int gid = lane >> 2, tig = lane & 3;
    const float* Vb = src + (((size_t)bh * S_) + kt * 64) * HD_;
    int k0 = ks2 * 16 + 2 * tig;
    int d  = pp * 16 + gid;
    float2 v0 = make_float2(Vb[(size_t)k0 * HD_ + d],       Vb[(size_t)(k0+1) * HD_ + d]);
    float2 v1 = make_float2(Vb[(size_t)(k0+8) * HD_ + d],   Vb[(size_t)(k0+9) * HD_ + d]);
    float2 v2 = make_float2(Vb[(size_t)k0 * HD_ + d + 8],   Vb[(size_t)(k0+1) * HD_ + d + 8]);
    float2 v3 = make_float2(Vb[(size_t)(k0+8) * HD_ + d+8], Vb[(size_t)(k0+9) * HD_ + d + 8]);
    uint4 lo;
    uint4 hi = pack4(v0, v1, v2, v3, lo);
    h4[g] = hi; l4[g] = lo;
}

// ---------------- bf16x3 GEMM, fragment-packed, cp.async 3-stage ---------------
// C[m,n] = sum_k A[m,k]*W[n,k]. 128x128 tile, BK=64, 256 threads (8 warps 2x4,
// warp 64x32). Stage = Ah|Al|Wh|Wl x 1024 uint4 = 64KB.
#define STU4 4096
#define STB  (STU4 * 16)
#define GEMM_SMEM_BYTES (3 * STB)

__global__ void __launch_bounds__(256) gemm3_kernel(
    const unsigned* __restrict__ AhB, const unsigned* __restrict__ AlB,
    const unsigned* __restrict__ WhB, const unsigned* __restrict__ WlB,
    float* __restrict__ Cout, int mode)
{
    extern __shared__ uint4 smq[];
    unsigned smb = (unsigned)__cvta_generic_to_shared(smq);

    int z = blockIdx.z;
    int tid = threadIdx.x, lane = tid & 31, warp = tid >> 5;
    int wmg = warp & 1, gq = warp >> 1;
    int wm = wmg * 64, wn = gq * 32;
    int gid = lane >> 2, tig = lane & 3;
    int tm = blockIdx.y, tn = blockIdx.x;
    int m0 = tm * 128, n0 = tn * 128;

    const uint4* Ahp = (const uint4*)AhB + (size_t)z * A_SLOT_U4 + ((size_t)tm * 32 << 10);
    const uint4* Alp = (const uint4*)AlB + (size_t)z * A_SLOT_U4 + ((size_t)tm * 32 << 10);
    const uint4* Whp = (const uint4*)WhB + (size_t)z * W_SLOT_U4 + ((size_t)tn * 32 << 10);
    const uint4* Wlp = (const uint4*)WlB + (size_t)z * W_SLOT_U4 + ((size_t)tn * 32 << 10);

    float acc[4][4][4];
#pragma unroll
    for (int mt = 0; mt < 4; mt++)
#pragma unroll
        for (int nt = 0; nt < 4; nt++)
#pragma unroll
            for (int e = 0; e < 4; e++) acc[mt][nt][e] = 0.f;

    const int NCHUNK = D_ / 64;          // 32

    auto issue = [&](int c, int st) {
        if (c < NCHUNK) {
            unsigned sb = smb + st * STB;
            size_t gb = (size_t)c << 10;
#pragma unroll
            for (int r = 0; r < 4; r++) {
                int idx = tid + 256 * r;
                cp16(sb + idx * 16,          Ahp + gb + idx);
                cp16(sb + (1024 + idx) * 16, Alp + gb + idx);
                cp16(sb + (2048 + idx) * 16, Whp + gb + idx);
                cp16(sb + (3072 + idx) * 16, Wlp + gb + idx);
            }
        }
        asm volatile("cp.async.commit_group;" ::: "memory");
    };

    issue(0, 0);
    issue(1, 1);

    for (int c = 0; c < NCHUNK; c++) {
        int st = c % 3;
        asm volatile("cp.async.wait_group 1;" ::: "memory");
        __syncthreads();
        issue(c + 2, (c + 2) % 3);

        const uint4* AsH = smq + st * STU4;
        const uint4* AsL = AsH + 1024;
        const uint4* WsH = AsL + 1024;
        const uint4* WsL = WsH + 1024;

#pragma unroll
        for (int ks = 0; ks < 4; ks++) {
            uint4 ah4[4], al4[4], wh4[2], wl4[2];
#pragma unroll
            for (int mt = 0; mt < 4; mt++) {
                int off = ((mt * 4 + ks) * 2 + wmg) * 32 + lane;
                ah4[mt] = AsH[off];
                al4[mt] = AsL[off];
            }
#pragma unroll
            for (int pp = 0; pp < 2; pp++) {
                int off = ((pp * 4 + ks) * 4 + gq) * 32 + lane;
                wh4[pp] = WsH[off];
                wl4[pp] = WsL[off];
            }
#pragma unroll
            for (int mt = 0; mt < 4; mt++)
#pragma unroll
                for (int pp = 0; pp < 2; pp++) {
                    unsigned bh0[2] = { wh4[pp].x, wh4[pp].y };
                    unsigned bh1[2] = { wh4[pp].z, wh4[pp].w };
                    unsigned bl0[2] = { wl4[pp].x, wl4[pp].y };
                    unsigned bl1[2] = { wl4[pp].z, wl4[pp].w };
                    const unsigned* a_h = (const unsigned*)&ah4[mt];
                    const unsigned* a_l = (const unsigned*)&al4[mt];
                    mma_bf16(acc[mt][2*pp],   a_h, bh0);
                    mma_bf16(acc[mt][2*pp],   a_h, bl0);
                    mma_bf16(acc[mt][2*pp],   a_l, bh0);
                    mma_bf16(acc[mt][2*pp+1], a_h, bh1);
                    mma_bf16(acc[mt][2*pp+1], a_h, bl1);
                    mma_bf16(acc[mt][2*pp+1], a_l, bh1);
                }
        }
    }

    float* C = (mode == 0) ? Cout : (z == 0 ? g_Q : (z == 1 ? g_K : g_V));

#pragma unroll
    for (int mt = 0; mt < 4; mt++) {
#pragma unroll
        for (int nt = 0; nt < 4; nt++) {
            int m = m0 + wm + mt * 16 + gid;
            int n = n0 + wn + nt * 8 + 2 * tig;
            float2 v0 = make_float2(acc[mt][nt][0], acc[mt][nt][1]);
            float2 v1 = make_float2(acc[mt][nt][2], acc[mt][nt][3]);
            if (mode == 0) {
                *(float2*)&C[(size_t)m * D_ + n]       = v0;
                *(float2*)&C[(size_t)(m + 8) * D_ + n] = v1;
            } else {
                int h = n >> 7, d = n & 127;
                int b = m >> 11, s = m & (S_ - 1);
                *(float2*)&C[(((size_t)b * H_ + h) * S_ + s) * HD_ + d] = v0;
                int m8 = m + 8;
                int b8 = m8 >> 11, s8 = m8 & (S_ - 1);
                *(float2*)&C[(((size_t)b8 * H_ + h) * S_ + s8) * HD_ + d] = v1;
            }
        }
    }
}

// ---------------- bf16x3 flash attention ---------------------------------------
// smem (uint4 units): QpH @0 (2048) | QpL @2048 | KpH @4096 (1024) | KpL @5120 |
// VpH @6144 | VpL @7168 | flags @8192 (int[8])
#define ATT_SMEM_BYTES (8192 * 16 + 32)

__global__ void __launch_bounds__(256) attn_tc2_kernel(
    const int* __restrict__ mask,
    const uint4* __restrict__ kHg, const uint4* __restrict__ kLg,
    const uint4* __restrict__ vHg, const uint4* __restrict__ vLg)
{
    extern __shared__ uint4 smq[];
    uint4* QpH = smq;
    uint4* QpL = smq + 2048;
    uint4* KpH = smq + 4096;
    uint4* KpL = smq + 5120;
    uint4* VpH = smq + 6144;
    uint4* VpL = smq + 7168;
    int* flagp = (int*)(smq + 8192);
    unsigned smk = (unsigned)__cvta_generic_to_shared(KpH);
    unsigned smv = (unsigned)__cvta_generic_to_shared(VpH);

    int bh = blockIdx.y;
    int b = bh >> 4, h = bh & 15;
    int q0 = blockIdx.x * 128;
    int tid = threadIdx.x;
    int lane = tid & 31;
    int warp = tid >> 5;
    int gid = lane >> 2, tig = lane & 3;
    int wm = warp * 16;
    const float scale = 0.08838834764831843f;   // 1/sqrt(128)

    const float* Qg = g_Q + (size_t)bh * S_ * HD_ + (size_t)q0 * HD_;
    const int*   Mg = mask + (size_t)b * S_ * S_ + (size_t)q0 * S_;
    const uint4* kH = kHg + (size_t)bh * 32768;   // 32 tiles x 1024
    const uint4* kL = kLg + (size_t)bh * 32768;
    const uint4* vH = vHg + (size_t)bh * 32768;
    const uint4* vL = vLg + (size_t)bh * 32768;

    auto issueK = [&](int t) {
        if (t < 32) {
            size_t base = (size_t)t * 1024;
#pragma unroll
            for (int r = 0; r < 4; r++) {
                int idx = tid + 256 * r;
                cp16(smk + idx * 16,         kH + base + idx);
                cp16(smk + 16384 + idx * 16, kL + base + idx);
            }
        }
        asm volatile("cp.async.commit_group;" ::: "memory");
    };
    auto issueV = [&](int t) {
        if (t < 32) {
            size_t base = (size_t)t * 1024;
#pragma unroll
            for (int r = 0; r < 4; r++) {
                int idx = tid + 256 * r;
                cp16(smv + idx * 16,         vH + base + idx);
                cp16(smv + 16384 + idx * 16, vL + base + idx);
            }
        }
        asm volatile("cp.async.commit_group;" ::: "memory");
    };

    issueK(0);
    issueV(0);

    // Pack Q (pre-scaled) into per-thread smem fragments (same-thread produce
    // and consume — no barrier needed).
#pragma unroll
    for (int ks = 0; ks < 8; ks++) {
        const float* qp = Qg + (size_t)(wm + gid) * HD_ + ks * 16 + 2 * tig;
        float2 u0 = *(const float2*)qp;
        float2 u1 = *(const float2*)(qp + 8 * HD_);
        float2 u2 = *(const float2*)(qp + 8);
        float2 u3 = *(const float2*)(qp + 8 * HD_ + 8);
        u0.x *= scale; u0.y *= scale; u1.x *= scale; u1.y *= scale;
        u2.x *= scale; u2.y *= scale; u3.x *= scale; u3.y *= scale;
        uint4 lo;
        uint4 hi = pack4(u0, u1, u2, u3, lo);
        QpH[(warp * 8 + ks) * 32 + lane] = hi;
        QpL[(warp * 8 + ks) * 32 + lane] = lo;
    }

    float m0 = -INFINITY, m1 = -INFINITY, l0 = 0.f, l1 = 0.f;
    float accO[16][4];
#pragma unroll
    for (int nt = 0; nt < 16; nt++)
#pragma unroll
        for (int e = 0; e < 4; e++) accO[nt][e] = 0.f;

    for (int t = 0; t < 32; t++) {
        int kt = t * 64;
        asm volatile("cp.async.wait_group 1;" ::: "memory");   // K(t) ready
        __syncthreads();

        // mask tile scan (flag published at next barrier)
        bool ok = true;
#pragma unroll
        for (int r = 0; r < 8; r++) {
            int idx = tid + 256 * r;
            int mrow = idx >> 4;
            int mc = (idx & 15) << 2;
            int4 mm = *(const int4*)(Mg + (size_t)mrow * S_ + kt + mc);
            ok = ok && (mm.x != 0) && (mm.y != 0) && (mm.z != 0) && (mm.w != 0);
        }
        unsigned bal = __ballot_sync(0xffffffffu, ok);
        if (lane == 0) flagp[warp] = (bal == 0xffffffffu) ? 1 : 0;

        // ---- S = (Q*scale) K^T  (16x64 per warp) ----
        float sacc[8][4];
#pragma unroll
        for (int nt = 0; nt < 8; nt++)
#pragma unroll
            for (int e = 0; e < 4; e++) sacc[nt][e] = 0.f;

#pragma unroll
        for (int ks = 0; ks < 8; ks++) {
            uint4 qh4 = QpH[(warp * 8 + ks) * 32 + lane];
            uint4 ql4 = QpL[(warp * 8 + ks) * 32 + lane];
            const unsigned* qh = (const unsigned*)&qh4;
            const unsigned* ql = (const unsigned*)&ql4;
#pragma unroll
            for (int pp = 0; pp < 4; pp++) {
                uint4 kh4 = KpH[(ks * 4 + pp) * 32 + lane];
                uint4 kl4 = KpL[(ks * 4 + pp) * 32 + lane];
                unsigned bh0[2] = { kh4.x, kh4.y };
                unsigned bh1[2] = { kh4.z, kh4.w };
                unsigned bl0[2] = { kl4.x, kl4.y };
                unsigned bl1[2] = { kl4.z, kl4.w };
                mma_bf16(sacc[2*pp],   qh, bh0);
                mma_bf16(sacc[2*pp],   qh, bl0);
                mma_bf16(sacc[2*pp],   ql, bh0);
                mma_bf16(sacc[2*pp+1], qh, bh1);
                mma_bf16(sacc[2*pp+1], qh, bl1);
                mma_bf16(sacc[2*pp+1], ql, bh1);
            }
        }
        __syncthreads();             // Kp reads done; flags visible

        int allones = flagp[0] & flagp[1] & flagp[2] & flagp[3]
                    & flagp[4] & flagp[5] & flagp[6] & flagp[7];
        if (!allones) {
            const int* M2 = mask + (size_t)b * S_ * S_;
#pragma unroll
            for (int nt = 0; nt < 8; nt++)
#pragma unroll
                for (int v = 0; v < 4; v++) {
                    int row = q0 + wm + gid + ((v >> 1) << 3);
                    int col = kt + nt * 8 + 2 * tig + (v & 1);
                    if (M2[(size_t)row * S_ + col] == 0) sacc[nt][v] = -1e30f;
                }
        }

        // ---- online softmax (warp-private) ----
        float mx0 = -INFINITY, mx1 = -INFINITY;
#pragma unroll
        for (int nt = 0; nt < 8; nt++) {
            mx0 = fmaxf(mx0, fmaxf(sacc[nt][0], sacc[nt][1]));
            mx1 = fmaxf(mx1, fmaxf(sacc[nt][2], sacc[nt][3]));
        }
        mx0 = fmaxf(mx0, __shfl_xor_sync(0xffffffffu, mx0, 1));
        mx0 = fmaxf(mx0, __shfl_xor_sync(0xffffffffu, mx0, 2));
        mx1 = fmaxf(mx1, __shfl_xor_sync(0xffffffffu, mx1, 1));
        mx1 = fmaxf(mx1, __shfl_xor_sync(0xffffffffu, mx1, 2));
        float mn0 = fmaxf(m0, mx0), mn1 = fmaxf(m1, mx1);
        float c0 = __expf(m0 - mn0), c1 = __expf(m1 - mn1);
        m0 = mn0; m1 = mn1;
        float s0 = 0.f, s1 = 0.f;
#pragma unroll
        for (int nt = 0; nt < 8; nt++) {
            sacc[nt][0] = __expf(sacc[nt][0] - mn0);
            sacc[nt][1] = __expf(sacc[nt][1] - mn0);
            sacc[nt][2] = __expf(sacc[nt][2] - mn1);
            sacc[nt][3] = __expf(sacc[nt][3] - mn1);
            s0 += sacc[nt][0] + sacc[nt][1];
            s1 += sacc[nt][2] + sacc[nt][3];
        }
        s0 += __shfl_xor_sync(0xffffffffu, s0, 1);
        s0 += __shfl_xor_sync(0xffffffffu, s0, 2);
        s1 += __shfl_xor_sync(0xffffffffu, s1, 1);
        s1 += __shfl_xor_sync(0xffffffffu, s1, 2);
        l0 = l0 * c0 + s0;
        l1 = l1 * c1 + s1;
#pragma unroll
        for (int nt = 0; nt < 16; nt++) {
            accO[nt][0] *= c0; accO[nt][1] *= c0;
            accO[nt][2] *= c1; accO[nt][3] *= c1;
        }

        issueK(t + 1);                                   // overlap with PV

        asm volatile("cp.async.wait_group 1;" ::: "memory");   // V(t) ready
        __syncthreads();

        // ---- O += P V : P a-frag IS the QK c-frag (m16n8k16 layout) ----
#pragma unroll
        for (int ks2 = 0; ks2 < 4; ks2++) {
            unsigned ph[4], pl[4];
            bf16_split2(sacc[2*ks2][0],   sacc[2*ks2][1],   ph[0], pl[0]);
            bf16_split2(sacc[2*ks2][2],   sacc[2*ks2][3],   ph[1], pl[1]);
            bf16_split2(sacc[2*ks2+1][0], sacc[2*ks2+1][1], ph[2], pl[2]);
            bf16_split2(sacc[2*ks2+1][2], sacc[2*ks2+1][3], ph[3], pl[3]);
#pragma unroll
            for (int pp = 0; pp < 8; pp++) {
                uint4 vh4 = VpH[(ks2 * 8 + pp) * 32 + lane];
                uint4 vl4 = VpL[(ks2 * 8 + pp) * 32 + lane];
                unsigned bh0[2] = { vh4.x, vh4.y };
                unsigned bh1[2] = { vh4.z, vh4.w };
                unsigned bl0[2] = { vl4.x, vl4.y };
                unsigned bl1[2] = { vl4.z, vl4.w };
                mma_bf16(accO[2*pp],   ph, bh0);
                mma_bf16(accO[2*pp],   pl, bh0);
                mma_bf16(accO[2*pp],   ph, bl0);
                mma_bf16(accO[2*pp+1], ph, bh1);
                mma_bf16(accO[2*pp+1], pl, bh1);
                mma_bf16(accO[2*pp+1], ph, bl1);
            }
        }
        __syncthreads();             // Vp reads done

        issueV(t + 1);
    }

    float inv0 = 1.0f / l0, inv1 = 1.0f / l1;
    float* Og = g_att + ((size_t)b * S_ + q0 + wm + gid) * D_ + h * HD_;
    float* Og8 = Og + 8 * D_;
#pragma unroll
    for (int nt = 0; nt < 16; nt++) {
        *(float2*)(Og + nt * 8 + 2 * tig) =
            make_float2(accO[nt][0] * inv0, accO[nt][1] * inv0);
        *(float2*)(Og8 + nt * 8 + 2 * tig) =
            make_float2(accO[nt][2] * inv1, accO[nt][3] * inv1);
    }
}

// ---------------- launch ------------------------------------------------------
extern "C" void kernel_launch(void* const* d_in, const int* in_sizes, int n_in,
                              void* d_out, int out_size)
{
    const float* query = (const float*)d_in[0];
    const float* key   = (const float*)d_in[1];
    const float* value = (const float*)d_in[2];
    const int*   mask  = (const int*)d_in[3];
    const float* wq    = (const float*)d_in[4];
    const float* wk    = (const float*)d_in[5];
    const float* wv    = (const float*)d_in[6];
    const float* wo    = (const float*)d_in[7];
    float* out = (float*)d_out;

    float *gA, *gK, *gV;
    unsigned *aH, *aL, *wH, *wL;
    cudaGetSymbolAddress((void**)&gA, g_att);
    cudaGetSymbolAddress((void**)&gK, g_K);
    cudaGetSymbolAddress((void**)&gV, g_V);
    cudaGetSymbolAddress((void**)&aH, g_actH);
    cudaGetSymbolAddress((void**)&aL, g_actL);
    cudaGetSymbolAddress((void**)&wH, g_wH);
    cudaGetSymbolAddress((void**)&wL, g_wL);

    cudaFuncSetAttribute(attn_tc2_kernel,
                         cudaFuncAttributeMaxDynamicSharedMemorySize,
                         ATT_SMEM_BYTES);
    cudaFuncSetAttribute(gemm3_kernel,
                         cudaFuncAttributeMaxDynamicSharedMemorySize,
                         GEMM_SMEM_BYTES);

    const size_t ASLOT = MK_ACT / 2;   // unsigneds per activation slot
    const size_t WSLOT = MK_W / 2;
    const int NAG = (int)(A_SLOT_U4 / 256);   // 4096
    const int NWG = (int)(W_SLOT_U4 / 256);   // 2048
    const int NKV = (int)(A_SLOT_U4 / 256);   // 4096 (1M uint4 per K/V buffer)

    // RoPE tables
    rope_tables_kernel<<<(S_ * 64 + 255) / 256, 256>>>();

    // Fragment-pack QKV activations + weights into slots 0..2
    packA_kernel<<<NAG, 256>>>(query, (uint4*)(aH), (uint4*)(aL));
    packA_kernel<<<NAG, 256>>>(key,   (uint4*)(aH + ASLOT), (uint4*)(aL + ASLOT));
    packA_kernel<<<NAG, 256>>>(value, (uint4*)(aH + 2 * ASLOT), (uint4*)(aL + 2 * ASLOT));
    packW_kernel<<<NWG, 256>>>(wq, (uint4*)(wH), (uint4*)(wL));
    packW_kernel<<<NWG, 256>>>(wk, (uint4*)(wH + WSLOT), (uint4*)(wL + WSLOT));
    packW_kernel<<<NWG, 256>>>(wv, (uint4*)(wH + 2 * WSLOT), (uint4*)(wL + 2 * WSLOT));

    // Fused Q/K/V projections (head layout)
    dim3 pg3(D_ / 128, (B_ * S_) / 128, 3);
    gemm3_kernel<<<pg3, 256, GEMM_SMEM_BYTES>>>(aH, aL, wH, wL, nullptr, 1);

    // RoPE on Q and K (in place)
    rope_apply_kernel<<<(2 * B_ * H_ * S_ * 64) / 256, 256>>>();

    // Pack roped K and V into attention fragment layout (reuse act slots 1,2)
    uint4* kHp = (uint4*)(aH + ASLOT);
    uint4* kLp = (uint4*)(aL + ASLOT);
    uint4* vHp = (uint4*)(aH + 2 * ASLOT);
    uint4* vLp = (uint4*)(aL + 2 * ASLOT);
    packK_kernel<<<NKV, 256>>>(gK, kHp, kLp);
    packV_kernel<<<NKV, 256>>>(gV, vHp, vLp);

    // Attention (bf16x3, pipelined)
    attn_tc2_kernel<<<dim3(S_ / 128, B_ * H_), 256, ATT_SMEM_BYTES>>>(
        mask, kHp, kLp, vHp, vLp);

    // Output projection: pack attention output + wo into slot 0, then GEMM
    packA_kernel<<<NAG, 256>>>(gA, (uint4*)(aH), (uint4*)(aL));
    packW_kernel<<<NWG, 256>>>(wo, (uint4*)(wH), (uint4*)(wL));
    dim3 pg1(D_ / 128, (B_ * S_) / 128, 1);
    gemm3_kernel<<<pg1, 256, GEMM_SMEM_BYTES>>>(aH, aL, wH, wL, out, 0);
}

// round 16
// speedup vs baseline: 2.2319x; 1.0421x over previous
#include <cuda_runtime.h>
#include <cuda_bf16.h>
#include <math.h>

#define B_  2
#define S_  2048
#define D_  2048
#define H_  16
#define HD_ 128

#define MK_ACT ((size_t)4096 * 2048)
#define MK_W   ((size_t)2048 * 2048)
#define A_SLOT_U4 (MK_ACT / 8)        // uint4 per activation slot (bf16 h or l)
#define W_SLOT_U4 (MK_W / 8)

// ---------------- scratch (device globals: no allocation allowed) -------------
__device__ float g_Q[(size_t)B_ * H_ * S_ * HD_];   // [B,H,S,hd]
__device__ float g_K[(size_t)B_ * H_ * S_ * HD_];
__device__ float g_V[(size_t)B_ * H_ * S_ * HD_];
__device__ float g_att[(size_t)B_ * S_ * D_];       // [B,S,D]
__device__ float g_cos[S_ * 64];
__device__ float g_sin[S_ * 64];
// fragment-packed bf16 hi/lo buffers (3 slots; slots 1,2 reused for packed K/V)
__device__ unsigned g_actH[3 * (MK_ACT / 2)];
__device__ unsigned g_actL[3 * (MK_ACT / 2)];
__device__ unsigned g_wH[3 * (MK_W / 2)];
__device__ unsigned g_wL[3 * (MK_W / 2)];

// ---------------- RoPE tables -------------------------------------------------
__global__ void rope_tables_kernel() {
    int idx = blockIdx.x * blockDim.x + threadIdx.x;
    if (idx >= S_ * 64) return;
    int s = idx >> 6, j = idx & 63;
    float invf = (float)(1.0 / pow(10000.0, (double)(2 * j) / 128.0));
    float ang_f = (float)s * invf;
    double ang = (double)ang_f;
    g_cos[idx] = (float)cos(ang);
    g_sin[idx] = (float)sin(ang);
}

__global__ void rope_apply_kernel() {
    int idx = blockIdx.x * blockDim.x + threadIdx.x;
    const int total = B_ * H_ * S_ * 64;
    float* T = (idx < total) ? g_Q : g_K;
    int p = (idx < total) ? idx : idx - total;
    int j = p & 63;
    int row = p >> 6;
    int s = row & (S_ - 1);
    size_t base = (size_t)row * HD_ + j;
    float c  = g_cos[(s << 6) + j];
    float sn = g_sin[(s << 6) + j];
    float x0 = T[base];
    float x1 = T[base + 64];
    T[base]      = x0 * c - x1 * sn;
    T[base + 64] = x1 * c + x0 * sn;
}

// ---------------- helpers ------------------------------------------------------
__device__ __forceinline__ void bf16_split2(float x0, float x1,
                                            unsigned &h2, unsigned &l2) {
    __nv_bfloat162 h = __floats2bfloat162_rn(x0, x1);
    float r0 = x0 - __bfloat162float(__low2bfloat16(h));
    float r1 = x1 - __bfloat162float(__high2bfloat16(h));
    __nv_bfloat162 l = __floats2bfloat162_rn(r0, r1);
    h2 = *reinterpret_cast<unsigned*>(&h);
    l2 = *reinterpret_cast<unsigned*>(&l);
}

__device__ __forceinline__ void mma_bf16(float* c, const unsigned* a, const unsigned* b) {
    asm volatile(
        "mma.sync.aligned.m16n8k16.row.col.f32.bf16.bf16.f32 "
        "{%0,%1,%2,%3}, {%4,%5,%6,%7}, {%8,%9}, {%0,%1,%2,%3};"
        : "+f"(c[0]), "+f"(c[1]), "+f"(c[2]), "+f"(c[3])
        : "r"(a[0]), "r"(a[1]), "r"(a[2]), "r"(a[3]), "r"(b[0]), "r"(b[1]));
}

__device__ __forceinline__ void cp16(unsigned dst, const void* src) {
    asm volatile("cp.async.cg.shared.global [%0], [%1], 16;" :: "r"(dst), "l"(src) : "memory");
}

__device__ __forceinline__ uint4 pack4(float2 v0, float2 v1, float2 v2, float2 v3,
                                       uint4 &lo) {
    uint4 hi;
    bf16_split2(v0.x, v0.y, hi.x, lo.x);
    bf16_split2(v1.x, v1.y, hi.y, lo.y);
    bf16_split2(v2.x, v2.y, hi.z, lo.z);
    bf16_split2(v3.x, v3.y, hi.w, lo.w);
    return hi;
}

// ---------------- fragment-pack kernels (GEMM operands, bf16, BK=32) -----------
// A: tiles 128(m) x 32(k); per (tm,c): 512 uint4. gi = ((mt*2+ks)*2+wmg)*32+lane
__global__ void __launch_bounds__(256) packA_kernel(
    const float* __restrict__ src, uint4* __restrict__ h4, uint4* __restrict__ l4)
{
    size_t g = (size_t)blockIdx.x * 256 + threadIdx.x;
    int gi = (int)(g & 511);
    size_t blk = g >> 9;
    int c  = (int)(blk & 63);
    int tm = (int)(blk >> 6);
    int lane = gi & 31, wmg = (gi >> 5) & 1, ks = (gi >> 6) & 1, mt = gi >> 7;
    int gid = lane >> 2, tig = lane & 3;
    int row = tm * 128 + wmg * 64 + mt * 16 + gid;
    int k   = c * 32 + ks * 16 + 2 * tig;
    const float* p = src + (size_t)row * D_ + k;
    uint4 lo;
    uint4 hi = pack4(*(const float2*)p, *(const float2*)(p + 8 * D_),
                     *(const float2*)(p + 8), *(const float2*)(p + 8 * D_ + 8), lo);
    h4[g] = hi; l4[g] = lo;
}

// W: tiles 128(n) x 32(k); gi = ((pp*2+ks)*4+gq)*32+lane
__global__ void __launch_bounds__(256) packW_kernel(
    const float* __restrict__ src, uint4* __restrict__ h4, uint4* __restrict__ l4)
{
    size_t g = (size_t)blockIdx.x * 256 + threadIdx.x;
    int gi = (int)(g & 511);
    size_t blk = g >> 9;
    int c  = (int)(blk & 63);
    int tn = (int)(blk >> 6);
    int lane = gi & 31, gq = (gi >> 5) & 3, ks = (gi >> 7) & 1, pp = gi >> 8;
    int gid = lane >> 2, tig = lane & 3;
    int n = tn * 128 + gq * 32 + pp * 16 + gid;
    int k = c * 32 + ks * 16 + 2 * tig;
    const float* p = src + (size_t)n * D_ + k;
    uint4 lo;
    uint4 hi = pack4(*(const float2*)p, *(const float2*)(p + 8),
                     *(const float2*)(p + 8 * D_), *(const float2*)(p + 8 * D_ + 8), lo);
    h4[g] = hi; l4[g] = lo;
}

// K (attention B of QK): per (bh,ktile): 1024 uint4. off = (ks*4+pp)*32+lane
__global__ void __launch_bounds__(256) packK_kernel(
    const float* __restrict__ src, uint4* __restrict__ h4, uint4* __restrict__ l4)
{
    size_t g = (size_t)blockIdx.x * 256 + threadIdx.x;
    int off = (int)(g & 1023);
    int kt  = (int)((g >> 10) & 31);
    int bh  = (int)(g >> 15);
    int lane = off & 31, pp = (off >> 5) & 3, ks = off >> 7;
    int gid = lane >> 2, tig = lane & 3;
    const float* Kb = src + (((size_t)bh * S_) + kt * 64) * HD_;
    int key = pp * 16 + gid;
    int d   = ks * 16 + 2 * tig;
    const float* p = Kb + (size_t)key * HD_ + d;
    uint4 lo;
    uint4 hi = pack4(*(const float2*)p, *(const float2*)(p + 8),
                     *(const float2*)(p + 8 * HD_), *(const float2*)(p + 8 * HD_ + 8), lo);
    h4[g] = hi; l4[g] = lo;
}

// V (attention B of PV): per (bh,ktile): 1024 uint4. off = (ks2*8+pp)*32+lane
__global__ void __launch_bounds__(256) packV_kernel(
    const float* __restrict__ src, uint4* __restrict__ h4, uint4* __restrict__ l4)
{
    size_t g = (size_t)blockIdx.x * 256 + threadIdx.x;
    int off = (int)(g & 1023);
    int kt  = (int)((g >> 10) & 31);
    int bh  = (int)(g >> 15);
    int lane = off & 31, pp = (off >> 5) & 7, ks2 = off >> 8;
    int gid = lane >> 2, tig = lane & 3;
    const float* Vb = src + (((size_t)bh * S_) + kt * 64) * HD_;
    int k0 = ks2 * 16 + 2 * tig;
    int d  = pp * 16 + gid;
    float2 v0 = make_float2(Vb[(size_t)k0 * HD_ + d],       Vb[(size_t)(k0+1) * HD_ + d]);
    float2 v1 = make_float2(Vb[(size_t)(k0+8) * HD_ + d],   Vb[(size_t)(k0+9) * HD_ + d]);
    float2 v2 = make_float2(Vb[(size_t)k0 * HD_ + d + 8],   Vb[(size_t)(k0+1) * HD_ + d + 8]);
    float2 v3 = make_float2(Vb[(size_t)(k0+8) * HD_ + d+8], Vb[(size_t)(k0+9) * HD_ + d + 8]);
    uint4 lo;
    uint4 hi = pack4(v0, v1, v2, v3, lo);
    h4[g] = hi; l4[g] = lo;
}

// ---------------- bf16x3 GEMM, BK=32, 3-stage, 2 CTAs/SM -----------------------
// Stage = Ah|Al|Wh|Wl x 512 uint4 = 32KB. 3 stages = 96KB -> 2 CTAs/SM.
#define STU4 2048
#define STB  (STU4 * 16)              // 32768
#define GEMM_SMEM_BYTES (3 * STB)     // 98304

__global__ void __launch_bounds__(256, 2) gemm3_kernel(
    const unsigned* __restrict__ AhB, const unsigned* __restrict__ AlB,
    const unsigned* __restrict__ WhB, const unsigned* __restrict__ WlB,
    float* __restrict__ Cout, int mode)
{
    extern __shared__ uint4 smq[];
    unsigned smb = (unsigned)__cvta_generic_to_shared(smq);

    int z = blockIdx.z;
    int tid = threadIdx.x, lane = tid & 31, warp = tid >> 5;
    int wmg = warp & 1, gq = warp >> 1;
    int wm = wmg * 64, wn = gq * 32;
    int gid = lane >> 2, tig = lane & 3;
    int tm = blockIdx.y, tn = blockIdx.x;
    int m0 = tm * 128, n0 = tn * 128;

    const uint4* Ahp = (const uint4*)AhB + (size_t)z * A_SLOT_U4 + ((size_t)tm << 15);
    const uint4* Alp = (const uint4*)AlB + (size_t)z * A_SLOT_U4 + ((size_t)tm << 15);
    const uint4* Whp = (const uint4*)WhB + (size_t)z * W_SLOT_U4 + ((size_t)tn << 15);
    const uint4* Wlp = (const uint4*)WlB + (size_t)z * W_SLOT_U4 + ((size_t)tn << 15);

    float acc[4][4][4];
#pragma unroll
    for (int mt = 0; mt < 4; mt++)
#pragma unroll
        for (int nt = 0; nt < 4; nt++)
#pragma unroll
            for (int e = 0; e < 4; e++) acc[mt][nt][e] = 0.f;

    const int NCHUNK = D_ / 32;          // 64

    auto issue = [&](int c, int st) {
        if (c < NCHUNK) {
            unsigned sb = smb + st * STB;
            size_t gb = (size_t)c << 9;
#pragma unroll
            for (int r = 0; r < 2; r++) {
                int idx = tid + 256 * r;
                cp16(sb + idx * 16,          Ahp + gb + idx);
                cp16(sb + (512 + idx) * 16,  Alp + gb + idx);
                cp16(sb + (1024 + idx) * 16, Whp + gb + idx);
                cp16(sb + (1536 + idx) * 16, Wlp + gb + idx);
            }
        }
        asm volatile("cp.async.commit_group;" ::: "memory");
    };

    issue(0, 0);
    issue(1, 1);

    for (int c = 0; c < NCHUNK; c++) {
        int st = c % 3;
        asm volatile("cp.async.wait_group 1;" ::: "memory");
        __syncthreads();
        issue(c + 2, (c + 2) % 3);

        const uint4* AsH = smq + st * STU4;
        const uint4* AsL = AsH + 512;
        const uint4* WsH = AsL + 512;
        const uint4* WsL = WsH + 512;

#pragma unroll
        for (int ks = 0; ks < 2; ks++) {
            uint4 ah4[4], al4[4], wh4[2], wl4[2];
#pragma unroll
            for (int mt = 0; mt < 4; mt++) {
                int off = ((mt * 2 + ks) * 2 + wmg) * 32 + lane;
                ah4[mt] = AsH[off];
                al4[mt] = AsL[off];
            }
#pragma unroll
            for (int pp = 0; pp < 2; pp++) {
                int off = ((pp * 2 + ks) * 4 + gq) * 32 + lane;
                wh4[pp] = WsH[off];
                wl4[pp] = WsL[off];
            }
#pragma unroll
            for (int mt = 0; mt < 4; mt++)
#pragma unroll
                for (int pp = 0; pp < 2; pp++) {
                    unsigned bh0[2] = { wh4[pp].x, wh4[pp].y };
                    unsigned bh1[2] = { wh4[pp].z, wh4[pp].w };
                    unsigned bl0[2] = { wl4[pp].x, wl4[pp].y };
                    unsigned bl1[2] = { wl4[pp].z, wl4[pp].w };
                    const unsigned* a_h = (const unsigned*)&ah4[mt];
                    const unsigned* a_l = (const unsigned*)&al4[mt];
                    mma_bf16(acc[mt][2*pp],   a_h, bh0);
                    mma_bf16(acc[mt][2*pp],   a_h, bl0);
                    mma_bf16(acc[mt][2*pp],   a_l, bh0);
                    mma_bf16(acc[mt][2*pp+1], a_h, bh1);
                    mma_bf16(acc[mt][2*pp+1], a_h, bl1);
                    mma_bf16(acc[mt][2*pp+1], a_l, bh1);
                }
        }
    }

    float* C = (mode == 0) ? Cout : (z == 0 ? g_Q : (z == 1 ? g_K : g_V));

#pragma unroll
    for (int mt = 0; mt < 4; mt++) {
#pragma unroll
        for (int nt = 0; nt < 4; nt++) {
            int m = m0 + wm + mt * 16 + gid;
            int n = n0 + wn + nt * 8 + 2 * tig;
            float2 v0 = make_float2(acc[mt][nt][0], acc[mt][nt][1]);
            float2 v1 = make_float2(acc[mt][nt][2], acc[mt][nt][3]);
            if (mode == 0) {
                *(float2*)&C[(size_t)m * D_ + n]       = v0;
                *(float2*)&C[(size_t)(m + 8) * D_ + n] = v1;
            } else {
                int h = n >> 7, d = n & 127;
                int b = m >> 11, s = m & (S_ - 1);
                *(float2*)&C[(((size_t)b * H_ + h) * S_ + s) * HD_ + d] = v0;
                int m8 = m + 8;
                int b8 = m8 >> 11, s8 = m8 & (S_ - 1);
                *(float2*)&C[(((size_t)b8 * H_ + h) * S_ + s8) * HD_ + d] = v1;
            }
        }
    }
}

// ---------------- bf16x3 flash attention (unchanged from R15 WIN) --------------
#define ATT_SMEM_BYTES (8192 * 16 + 32)

__global__ void __launch_bounds__(256) attn_tc2_kernel(
    const int* __restrict__ mask,
    const uint4* __restrict__ kHg, const uint4* __restrict__ kLg,
    const uint4* __restrict__ vHg, const uint4* __restrict__ vLg)
{
    extern __shared__ uint4 smq[];
    uint4* QpH = smq;
    uint4* QpL = smq + 2048;
    uint4* KpH = smq + 4096;
    uint4* KpL = smq + 5120;
    uint4* VpH = smq + 6144;
    uint4* VpL = smq + 7168;
    int* flagp = (int*)(smq + 8192);
    unsigned smk = (unsigned)__cvta_generic_to_shared(KpH);
    unsigned smv = (unsigned)__cvta_generic_to_shared(VpH);

    int bh = blockIdx.y;
    int b = bh >> 4, h = bh & 15;
    int q0 = blockIdx.x * 128;
    int tid = threadIdx.x;
    int lane = tid & 31;
    int warp = tid >> 5;
    int gid = lane >> 2, tig = lane & 3;
    int wm = warp * 16;
    const float scale = 0.08838834764831843f;   // 1/sqrt(128)

    const float* Qg = g_Q + (size_t)bh * S_ * HD_ + (size_t)q0 * HD_;
    const int*   Mg = mask + (size_t)b * S_ * S_ + (size_t)q0 * S_;
    const uint4* kH = kHg + (size_t)bh * 32768;
    const uint4* kL = kLg + (size_t)bh * 32768;
    const uint4* vH = vHg + (size_t)bh * 32768;
    const uint4* vL = vLg + (size_t)bh * 32768;

    auto issueK = [&](int t) {
        if (t < 32) {
            size_t base = (size_t)t * 1024;
#pragma unroll
            for (int r = 0; r < 4; r++) {
                int idx = tid + 256 * r;
                cp16(smk + idx * 16,         kH + base + idx);
                cp16(smk + 16384 + idx * 16, kL + base + idx);
            }
        }
        asm volatile("cp.async.commit_group;" ::: "memory");
    };
    auto issueV = [&](int t) {
        if (t < 32) {
            size_t base = (size_t)t * 1024;
#pragma unroll
            for (int r = 0; r < 4; r++) {
                int idx = tid + 256 * r;
                cp16(smv + idx * 16,         vH + base + idx);
                cp16(smv + 16384 + idx * 16, vL + base + idx);
            }
        }
        asm volatile("cp.async.commit_group;" ::: "memory");
    };

    issueK(0);
    issueV(0);

#pragma unroll
    for (int ks = 0; ks < 8; ks++) {
        const float* qp = Qg + (size_t)(wm + gid) * HD_ + ks * 16 + 2 * tig;
        float2 u0 = *(const float2*)qp;
        float2 u1 = *(const float2*)(qp + 8 * HD_);
        float2 u2 = *(const float2*)(qp + 8);
        float2 u3 = *(const float2*)(qp + 8 * HD_ + 8);
        u0.x *= scale; u0.y *= scale; u1.x *= scale; u1.y *= scale;
        u2.x *= scale; u2.y *= scale; u3.x *= scale; u3.y *= scale;
        uint4 lo;
        uint4 hi = pack4(u0, u1, u2, u3, lo);
        QpH[(warp * 8 + ks) * 32 + lane] = hi;
        QpL[(warp * 8 + ks) * 32 + lane] = lo;
    }

    float m0 = -INFINITY, m1 = -INFINITY, l0 = 0.f, l1 = 0.f;
    float accO[16][4];
#pragma unroll
    for (int nt = 0; nt < 16; nt++)
#pragma unroll
        for (int e = 0; e < 4; e++) accO[nt][e] = 0.f;

    for (int t = 0; t < 32; t++) {
        int kt = t * 64;
        asm volatile("cp.async.wait_group 1;" ::: "memory");
        __syncthreads();

        bool ok = true;
#pragma unroll
        for (int r = 0; r < 8; r++) {
            int idx = tid + 256 * r;
            int mrow = idx >> 4;
            int mc = (idx & 15) << 2;
            int4 mm = *(const int4*)(Mg + (size_t)mrow * S_ + kt + mc);
            ok = ok && (mm.x != 0) && (mm.y != 0) && (mm.z != 0) && (mm.w != 0);
        }
        unsigned bal = __ballot_sync(0xffffffffu, ok);
        if (lane == 0) flagp[warp] = (bal == 0xffffffffu) ? 1 : 0;

        float sacc[8][4];
#pragma unroll
        for (int nt = 0; nt < 8; nt++)
#pragma unroll
            for (int e = 0; e < 4; e++) sacc[nt][e] = 0.f;

#pragma unroll
        for (int ks = 0; ks < 8; ks++) {
            uint4 qh4 = QpH[(warp * 8 + ks) * 32 + lane];
            uint4 ql4 = QpL[(warp * 8 + ks) * 32 + lane];
            const unsigned* qh = (const unsigned*)&qh4;
            const unsigned* ql = (const unsigned*)&ql4;
#pragma unroll
            for (int pp = 0; pp < 4; pp++) {
                uint4 kh4 = KpH[(ks * 4 + pp) * 32 + lane];
                uint4 kl4 = KpL[(ks * 4 + pp) * 32 + lane];
                unsigned bh0[2] = { kh4.x, kh4.y };
                unsigned bh1[2] = { kh4.z, kh4.w };
                unsigned bl0[2] = { kl4.x, kl4.y };
                unsigned bl1[2] = { kl4.z, kl4.w };
                mma_bf16(sacc[2*pp],   qh, bh0);
                mma_bf16(sacc[2*pp],   qh, bl0);
                mma_bf16(sacc[2*pp],   ql, bh0);
                mma_bf16(sacc[2*pp+1], qh, bh1);
                mma_bf16(sacc[2*pp+1], qh, bl1);
                mma_bf16(sacc[2*pp+1], ql, bh1);
            }
        }
        __syncthreads();

        int allones = flagp[0] & flagp[1] & flagp[2] & flagp[3]
                    & flagp[4] & flagp[5] & flagp[6] & flagp[7];
        if (!allones) {
            const int* M2 = mask + (size_t)b * S_ * S_;
#pragma unroll
            for (int nt = 0; nt < 8; nt++)
#pragma unroll
                for (int v = 0; v < 4; v++) {
                    int row = q0 + wm + gid + ((v >> 1) << 3);
                    int col = kt + nt * 8 + 2 * tig + (v & 1);
                    if (M2[(size_t)row * S_ + col] == 0) sacc[nt][v] = -1e30f;
                }
        }

        float mx0 = -INFINITY, mx1 = -INFINITY;
#pragma unroll
        for (int nt = 0; nt < 8; nt++) {
            mx0 = fmaxf(mx0, fmaxf(sacc[nt][0], sacc[nt][1]));
            mx1 = fmaxf(mx1, fmaxf(sacc[nt][2], sacc[nt][3]));
        }
        mx0 = fmaxf(mx0, __shfl_xor_sync(0xffffffffu, mx0, 1));
        mx0 = fmaxf(mx0, __shfl_xor_sync(0xffffffffu, mx0, 2));
        mx1 = fmaxf(mx1, __shfl_xor_sync(0xffffffffu, mx1, 1));
        mx1 = fmaxf(mx1, __shfl_xor_sync(0xffffffffu, mx1, 2));
        float mn0 = fmaxf(m0, mx0), mn1 = fmaxf(m1, mx1);
        float c0 = __expf(m0 - mn0), c1 = __expf(m1 - mn1);
        m0 = mn0; m1 = mn1;
        float s0 = 0.f, s1 = 0.f;
#pragma unroll
        for (int nt = 0; nt < 8; nt++) {
            sacc[nt][0] = __expf(sacc[nt][0] - mn0);
            sacc[nt][1] = __expf(sacc[nt][1] - mn0);
            sacc[nt][2] = __expf(sacc[nt][2] - mn1);
            sacc[nt][3] = __expf(sacc[nt][3] - mn1);
            s0 += sacc[nt][0] + sacc[nt][1];
            s1 += sacc[nt][2] + sacc[nt][3];
        }
        s0 += __shfl_xor_sync(0xffffffffu, s0, 1);
        s0 += __shfl_xor_sync(0xffffffffu, s0, 2);
        s1 += __shfl_xor_sync(0xffffffffu, s1, 1);
        s1 += __shfl_xor_sync(0xffffffffu, s1, 2);
        l0 = l0 * c0 + s0;
        l1 = l1 * c1 + s1;
#pragma unroll
        for (int nt = 0; nt < 16; nt++) {
            accO[nt][0] *= c0; accO[nt][1] *= c0;
            accO[nt][2] *= c1; accO[nt][3] *= c1;
        }

        issueK(t + 1);

        asm volatile("cp.async.wait_group 1;" ::: "memory");
        __syncthreads();

#pragma unroll
        for (int ks2 = 0; ks2 < 4; ks2++) {
            unsigned ph[4], pl[4];
            bf16_split2(sacc[2*ks2][0],   sacc[2*ks2][1],   ph[0], pl[0]);
            bf16_split2(sacc[2*ks2][2],   sacc[2*ks2][3],   ph[1], pl[1]);
            bf16_split2(sacc[2*ks2+1][0], sacc[2*ks2+1][1], ph[2], pl[2]);
            bf16_split2(sacc[2*ks2+1][2], sacc[2*ks2+1][3], ph[3], pl[3]);
#pragma unroll
            for (int pp = 0; pp < 8; pp++) {
                uint4 vh4 = VpH[(ks2 * 8 + pp) * 32 + lane];
                uint4 vl4 = VpL[(ks2 * 8 + pp) * 32 + lane];
                unsigned bh0[2] = { vh4.x, vh4.y };
                unsigned bh1[2] = { vh4.z, vh4.w };
                unsigned bl0[2] = { vl4.x, vl4.y };
                unsigned bl1[2] = { vl4.z, vl4.w };
                mma_bf16(accO[2*pp],   ph, bh0);
                mma_bf16(accO[2*pp],   pl, bh0);
                mma_bf16(accO[2*pp],   ph, bl0);
                mma_bf16(accO[2*pp+1], ph, bh1);
                mma_bf16(accO[2*pp+1], pl, bh1);
                mma_bf16(accO[2*pp+1], ph, bl1);
            }
        }
        __syncthreads();

        issueV(t + 1);
    }

    float inv0 = 1.0f / l0, inv1 = 1.0f / l1;
    float* Og = g_att + ((size_t)b * S_ + q0 + wm + gid) * D_ + h * HD_;
    float* Og8 = Og + 8 * D_;
#pragma unroll
    for (int nt = 0; nt < 16; nt++) {
        *(float2*)(Og + nt * 8 + 2 * tig) =
            make_float2(accO[nt][0] * inv0, accO[nt][1] * inv0);
        *(float2*)(Og8 + nt * 8 + 2 * tig) =
            make_float2(accO[nt][2] * inv1, accO[nt][3] * inv1);
    }
}

// ---------------- launch ------------------------------------------------------
extern "C" void kernel_launch(void* const* d_in, const int* in_sizes, int n_in,
                              void* d_out, int out_size)
{
    const float* query = (const float*)d_in[0];
    const float* key   = (const float*)d_in[1];
    const float* value = (const float*)d_in[2];
    const int*   mask  = (const int*)d_in[3];
    const float* wq    = (const float*)d_in[4];
    const float* wk    = (const float*)d_in[5];
    const float* wv    = (const float*)d_in[6];
    const float* wo    = (const float*)d_in[7];
    float* out = (float*)d_out;

    float *gA, *gK, *gV;
    unsigned *aH, *aL, *wH, *wL;
    cudaGetSymbolAddress((void**)&gA, g_att);
    cudaGetSymbolAddress((void**)&gK, g_K);
    cudaGetSymbolAddress((void**)&gV, g_V);
    cudaGetSymbolAddress((void**)&aH, g_actH);
    cudaGetSymbolAddress((void**)&aL, g_actL);
    cudaGetSymbolAddress((void**)&wH, g_wH);
    cudaGetSymbolAddress((void**)&wL, g_wL);

    cudaFuncSetAttribute(attn_tc2_kernel,
                         cudaFuncAttributeMaxDynamicSharedMemorySize,
                         ATT_SMEM_BYTES);
    cudaFuncSetAttribute(gemm3_kernel,
                         cudaFuncAttributeMaxDynamicSharedMemorySize,
                         GEMM_SMEM_BYTES);

    const size_t ASLOT = MK_ACT / 2;   // unsigneds per activation slot
    const size_t WSLOT = MK_W / 2;
    const int NAG = (int)(A_SLOT_U4 / 256);   // 4096
    const int NWG = (int)(W_SLOT_U4 / 256);   // 2048
    const int NKV = (int)(A_SLOT_U4 / 256);   // 4096

    // RoPE tables
    rope_tables_kernel<<<(S_ * 64 + 255) / 256, 256>>>();

    // Fragment-pack QKV activations + weights into slots 0..2
    packA_kernel<<<NAG, 256>>>(query, (uint4*)(aH), (uint4*)(aL));
    packA_kernel<<<NAG, 256>>>(key,   (uint4*)(aH + ASLOT), (uint4*)(aL + ASLOT));
    packA_kernel<<<NAG, 256>>>(value, (uint4*)(aH + 2 * ASLOT), (uint4*)(aL + 2 * ASLOT));
    packW_kernel<<<NWG, 256>>>(wq, (uint4*)(wH), (uint4*)(wL));
    packW_kernel<<<NWG, 256>>>(wk, (uint4*)(wH + WSLOT), (uint4*)(wL + WSLOT));
    packW_kernel<<<NWG, 256>>>(wv, (uint4*)(wH + 2 * WSLOT), (uint4*)(wL + 2 * WSLOT));

    // Fused Q/K/V projections (head layout)
    dim3 pg3(D_ / 128, (B_ * S_) / 128, 3);
    gemm3_kernel<<<pg3, 256, GEMM_SMEM_BYTES>>>(aH, aL, wH, wL, nullptr, 1);

    // RoPE on Q and K (in place)
    rope_apply_kernel<<<(2 * B_ * H_ * S_ * 64) / 256, 256>>>();

    // Pack roped K and V into attention fragment layout (reuse act slots 1,2)
    uint4* kHp = (uint4*)(aH + ASLOT);
    uint4* kLp = (uint4*)(aL + ASLOT);
    uint4* vHp = (uint4*)(aH + 2 * ASLOT);
    uint4* vLp = (uint4*)(aL + 2 * ASLOT);
    packK_kernel<<<NKV, 256>>>(gK, kHp, kLp);
    packV_kernel<<<NKV, 256>>>(gV, vHp, vLp);

    // Attention (bf16x3, pipelined)
    attn_tc2_kernel<<<dim3(S_ / 128, B_ * H_), 256, ATT_SMEM_BYTES>>>(
        mask, kHp, kLp, vHp, vLp);

    // Output projection: pack attention output + wo into slot 0, then GEMM
    packA_kernel<<<NAG, 256>>>(gA, (uint4*)(aH), (uint4*)(aL));
    packW_kernel<<<NWG, 256>>>(wo, (uint4*)(wH), (uint4*)(wL));
    dim3 pg1(D_ / 128, (B_ * S_) / 128, 1);
    gemm3_kernel<<<pg1, 256, GEMM_SMEM_BYTES>>>(aH, aL, wH, wL, out, 0);
}